// round 1
// baseline (speedup 1.0000x reference)
#include <cuda_runtime.h>
#include <math.h>

#define NN 50000
#define EE 800000
#define FIN 165

// ---------------- scratch (device globals; no allocation allowed) ----------------
__device__ float g_buf1[NN * 256];
__device__ float g_buf2[NN * 256];
__device__ float g_buf3[NN * 256];
__device__ float g_xinit[NN * 128];
__device__ float g_asrc[NN * 8];
__device__ float g_adst[NN * 8];
__device__ int   g_rowptr[NN + 1];
__device__ int   g_deg[NN];
__device__ int   g_col[EE];

// ---------------- CSR build (by destination) ----------------
__global__ void k_zero_deg(int n) {
    int i = blockIdx.x * blockDim.x + threadIdx.x;
    if (i < n) g_deg[i] = 0;
}

__global__ void k_count(const int* __restrict__ dst, int e) {
    int i = blockIdx.x * blockDim.x + threadIdx.x;
    if (i < e) atomicAdd(&g_deg[dst[i]], 1);
}

// single-block exclusive scan over g_deg -> g_rowptr
__global__ void k_scan(int n) {
    __shared__ int sh[1024];
    int t = threadIdx.x;
    int C = (n + 1023) / 1024;
    int base = t * C;
    int local = 0;
    for (int j = 0; j < C; j++) {
        int i = base + j;
        if (i < n) local += g_deg[i];
    }
    sh[t] = local;
    __syncthreads();
    for (int off = 1; off < 1024; off <<= 1) {
        int v = (t >= off) ? sh[t - off] : 0;
        __syncthreads();
        sh[t] += v;
        __syncthreads();
    }
    int run = sh[t] - local;  // exclusive prefix
    for (int j = 0; j < C; j++) {
        int i = base + j;
        if (i < n) { g_rowptr[i] = run; run += g_deg[i]; }
    }
    if (t == 1023) g_rowptr[n] = sh[1023];
}

__global__ void k_scatter(const int* __restrict__ src, const int* __restrict__ dst, int e) {
    int i = blockIdx.x * blockDim.x + threadIdx.x;
    if (i >= e) return;
    int d = dst[i];
    int pos = g_rowptr[d] + atomicAdd(&g_deg[d], 1);
    g_col[pos] = src[i];
}

// ---------------- SGEMM: C[M,N] = A[M,K] @ B[K,N] (*scale) (+bias) ----------------
// BM=128, BN=64, BK=8, 256 threads, 8x4 per-thread microtile.
__global__ void k_sgemm(const float* __restrict__ A, const float* __restrict__ B,
                        float* __restrict__ C, int M, int N, int K,
                        const float* __restrict__ bias, const float* __restrict__ scale) {
    __shared__ float As[8][128];
    __shared__ float Bs[8][64];
    int tid = threadIdx.x;
    int tx = tid & 15;   // 0..15 -> cols
    int ty = tid >> 4;   // 0..15 -> rows
    int bm = blockIdx.y * 128;
    int bn = blockIdx.x * 64;

    float acc[8][4];
#pragma unroll
    for (int i = 0; i < 8; i++)
#pragma unroll
        for (int j = 0; j < 4; j++) acc[i][j] = 0.f;

    for (int k0 = 0; k0 < K; k0 += 8) {
#pragma unroll
        for (int j = 0; j < 4; j++) {
            int idx = tid + j * 256;          // 0..1023
            int r = idx >> 3;
            int k = idx & 7;
            int gr = bm + r, gk = k0 + k;
            As[k][r] = (gr < M && gk < K) ? A[(size_t)gr * K + gk] : 0.f;
        }
#pragma unroll
        for (int j = 0; j < 2; j++) {
            int idx = tid + j * 256;          // 0..511
            int k = idx >> 6;
            int c = idx & 63;
            int gk = k0 + k, gc = bn + c;
            Bs[k][c] = (gk < K && gc < N) ? B[(size_t)gk * N + gc] : 0.f;
        }
        __syncthreads();
#pragma unroll
        for (int kk = 0; kk < 8; kk++) {
            float a[8], b[4];
#pragma unroll
            for (int i = 0; i < 8; i++) a[i] = As[kk][ty * 8 + i];
#pragma unroll
            for (int j = 0; j < 4; j++) b[j] = Bs[kk][tx * 4 + j];
#pragma unroll
            for (int i = 0; i < 8; i++)
#pragma unroll
                for (int j = 0; j < 4; j++) acc[i][j] = fmaf(a[i], b[j], acc[i][j]);
        }
        __syncthreads();
    }

    float scl = scale ? *scale : 1.0f;
#pragma unroll
    for (int i = 0; i < 8; i++) {
        int gr = bm + ty * 8 + i;
        if (gr >= M) continue;
#pragma unroll
        for (int j = 0; j < 4; j++) {
            int gc = bn + tx * 4 + j;
            if (gc < N) {
                float v = acc[i][j] * scl;
                if (bias) v += bias[gc];
                C[(size_t)gr * N + gc] = v;
            }
        }
    }
}

// ---------------- attention dot products: asrc/adst [n,H] ----------------
__global__ void k_attn(const float* __restrict__ h, const float* __restrict__ as_,
                       const float* __restrict__ ad_, int n, int H) {
    int w = (blockIdx.x * blockDim.x + threadIdx.x) >> 5;
    int l = threadIdx.x & 31;
    if (w >= n) return;
    const float* hr = h + (size_t)w * H * 32;
    for (int c = 0; c < H; c++) {
        float v = hr[c * 32 + l];
        float ps = v * as_[c * 32 + l];
        float pd = v * ad_[c * 32 + l];
#pragma unroll
        for (int o = 16; o; o >>= 1) {
            ps += __shfl_down_sync(0xffffffffu, ps, o);
            pd += __shfl_down_sync(0xffffffffu, pd, o);
        }
        if (l == 0) { g_asrc[w * H + c] = ps; g_adst[w * H + c] = pd; }
    }
}

// ---------------- GAT segment-softmax aggregation (warp per node) ----------------
template <int H, bool SL>
__global__ void k_agg(const float* __restrict__ h, const float* __restrict__ bias,
                      float* __restrict__ out, int n) {
    const int D = H * 32;
    int w = (blockIdx.x * blockDim.x + threadIdx.x) >> 5;
    int l = threadIdx.x & 31;
    if (w >= n) return;
    int hA = l >> 3;                 // head for dims [4l, 4l+4)
    float adA = g_adst[w * H + hA];
    float adB = 0.f;
    if (H == 8) adB = g_adst[w * H + 4 + hA];   // head for dims [128+4l, ...)
    int rs = g_rowptr[w], re = g_rowptr[w + 1];

    float mxA = -1e30f, mxB = -1e30f;
    float esA = 0.f, esB = 0.f;
    if (SL) {
        float t = g_asrc[w * H + hA] + adA; esA = (t > 0.f) ? t : 0.2f * t; mxA = esA;
        if (H == 8) { float u = g_asrc[w * H + 4 + hA] + adB; esB = (u > 0.f) ? u : 0.2f * u; mxB = esB; }
    }
    for (int j = rs; j < re; j++) {
        int s = g_col[j];
        float t = g_asrc[s * H + hA] + adA; t = (t > 0.f) ? t : 0.2f * t; mxA = fmaxf(mxA, t);
        if (H == 8) { float u = g_asrc[s * H + 4 + hA] + adB; u = (u > 0.f) ? u : 0.2f * u; mxB = fmaxf(mxB, u); }
    }

    float denA = 0.f, denB = 0.f;
    float4 aA = make_float4(0.f, 0.f, 0.f, 0.f);
    float4 aB = make_float4(0.f, 0.f, 0.f, 0.f);
    if (SL) {
        float ex = __expf(esA - mxA); denA += ex;
        float4 v = *(const float4*)(h + (size_t)w * D + 4 * l);
        aA.x += ex * v.x; aA.y += ex * v.y; aA.z += ex * v.z; aA.w += ex * v.w;
        if (H == 8) {
            float ex2 = __expf(esB - mxB); denB += ex2;
            float4 u = *(const float4*)(h + (size_t)w * D + 128 + 4 * l);
            aB.x += ex2 * u.x; aB.y += ex2 * u.y; aB.z += ex2 * u.z; aB.w += ex2 * u.w;
        }
    }
    for (int j = rs; j < re; j++) {
        int s = g_col[j];
        float t = g_asrc[s * H + hA] + adA; t = (t > 0.f) ? t : 0.2f * t;
        float ex = __expf(t - mxA); denA += ex;
        float4 v = *(const float4*)(h + (size_t)s * D + 4 * l);
        aA.x += ex * v.x; aA.y += ex * v.y; aA.z += ex * v.z; aA.w += ex * v.w;
        if (H == 8) {
            float u = g_asrc[s * H + 4 + hA] + adB; u = (u > 0.f) ? u : 0.2f * u;
            float ex2 = __expf(u - mxB); denB += ex2;
            float4 q = *(const float4*)(h + (size_t)s * D + 128 + 4 * l);
            aB.x += ex2 * q.x; aB.y += ex2 * q.y; aB.z += ex2 * q.z; aB.w += ex2 * q.w;
        }
    }

    float sA = 1.f / (denA + 1e-16f);
    float4 b4 = *(const float4*)(bias + 4 * l);
    float4 o;
    o.x = aA.x * sA + b4.x; o.y = aA.y * sA + b4.y; o.z = aA.z * sA + b4.z; o.w = aA.w * sA + b4.w;
    *(float4*)(out + (size_t)w * D + 4 * l) = o;
    if (H == 8) {
        float sB = 1.f / (denB + 1e-16f);
        float4 b42 = *(const float4*)(bias + 128 + 4 * l);
        float4 o2;
        o2.x = aB.x * sB + b42.x; o2.y = aB.y * sB + b42.y; o2.z = aB.z * sB + b42.z; o2.w = aB.w * sB + b42.w;
        *(float4*)(out + (size_t)w * D + 128 + 4 * l) = o2;
    }
}

// ---------------- BN(eval) + optional residual + ELU, in place ----------------
__global__ void k_bn_elu(float* __restrict__ x, const float* __restrict__ g,
                         const float* __restrict__ be, const float* __restrict__ m,
                         const float* __restrict__ v, const float* __restrict__ resid,
                         int total, int Dmask) {
    int idx = blockIdx.x * blockDim.x + threadIdx.x;
    if (idx >= total) return;
    int d = idx & Dmask;  // D is power of two
    float val = (x[idx] - m[d]) * rsqrtf(v[d] + 1e-5f) * g[d] + be[d];
    if (resid) val += resid[idx];
    x[idx] = (val > 0.f) ? val : expm1f(val);
}

// ---------------- final: (h3 + x_init) @ fcW + fcb, log_softmax ----------------
__global__ void k_final(const float* __restrict__ h3, const float* __restrict__ xi,
                        const float* __restrict__ fcW, const float* __restrict__ fcb,
                        float* __restrict__ out, int n) {
    int w = (blockIdx.x * blockDim.x + threadIdx.x) >> 5;
    int l = threadIdx.x & 31;
    if (w >= n) return;
    float4 a = *(const float4*)(h3 + (size_t)w * 128 + 4 * l);
    float4 b = *(const float4*)(xi + (size_t)w * 128 + 4 * l);
    float v0 = a.x + b.x, v1 = a.y + b.y, v2 = a.z + b.z, v3 = a.w + b.w;
    int d = 4 * l;
    float z0 = v0 * fcW[d * 2]     + v1 * fcW[(d + 1) * 2]     + v2 * fcW[(d + 2) * 2]     + v3 * fcW[(d + 3) * 2];
    float z1 = v0 * fcW[d * 2 + 1] + v1 * fcW[(d + 1) * 2 + 1] + v2 * fcW[(d + 2) * 2 + 1] + v3 * fcW[(d + 3) * 2 + 1];
#pragma unroll
    for (int o = 16; o; o >>= 1) {
        z0 += __shfl_down_sync(0xffffffffu, z0, o);
        z1 += __shfl_down_sync(0xffffffffu, z1, o);
    }
    if (l == 0) {
        z0 += fcb[0]; z1 += fcb[1];
        float mx = fmaxf(z0, z1);
        float lse = mx + logf(expf(z0 - mx) + expf(z1 - mx));
        out[w * 2] = z0 - lse;
        out[w * 2 + 1] = z1 - lse;
    }
}

// ---------------- launch ----------------
extern "C" void kernel_launch(void* const* d_in, const int* in_sizes, int n_in,
                              void* d_out, int out_size) {
    const float* x   = (const float*)d_in[0];
    const int*   ei  = (const int*)d_in[1];
    const float* W1  = (const float*)d_in[2];
    const float* a1s = (const float*)d_in[3];
    const float* a1d = (const float*)d_in[4];
    const float* b1  = (const float*)d_in[5];
    const float* g1  = (const float*)d_in[6];
    const float* be1 = (const float*)d_in[7];
    const float* m1  = (const float*)d_in[8];
    const float* v1  = (const float*)d_in[9];
    const float* W2  = (const float*)d_in[10];
    const float* a2s = (const float*)d_in[11];
    const float* a2d = (const float*)d_in[12];
    const float* b2  = (const float*)d_in[13];
    const float* g2  = (const float*)d_in[14];
    const float* be2 = (const float*)d_in[15];
    const float* m2  = (const float*)d_in[16];
    const float* v2  = (const float*)d_in[17];
    const float* W3  = (const float*)d_in[18];
    const float* a3s = (const float*)d_in[19];
    const float* a3d = (const float*)d_in[20];
    const float* b3  = (const float*)d_in[21];
    const float* fcW = (const float*)d_in[22];
    const float* fcb = (const float*)d_in[23];
    const float* skW = (const float*)d_in[24];
    const float* skb = (const float*)d_in[25];
    const float* temp = (const float*)d_in[26];

    int n = in_sizes[0] / FIN;   // 50000
    int e = in_sizes[1] / 2;     // 800000
    const int* src = ei;
    const int* dst = ei + e;

    float *buf1, *buf2, *buf3, *xinit;
    cudaGetSymbolAddress((void**)&buf1, g_buf1);
    cudaGetSymbolAddress((void**)&buf2, g_buf2);
    cudaGetSymbolAddress((void**)&buf3, g_buf3);
    cudaGetSymbolAddress((void**)&xinit, g_xinit);

    int nb256 = (n + 255) / 256;
    int eb256 = (e + 255) / 256;
    int warpGrid = (n * 32 + 255) / 256;

    // CSR build (by destination)
    k_zero_deg<<<nb256, 256>>>(n);
    k_count<<<eb256, 256>>>(dst, e);
    k_scan<<<1, 1024>>>(n);
    k_zero_deg<<<nb256, 256>>>(n);
    k_scatter<<<eb256, 256>>>(src, dst, e);

    dim3 gemmGrid1((128 + 63) / 64, (n + 127) / 128);
    dim3 gemmGrid2((256 + 63) / 64, (n + 127) / 128);

    // skip connection: x_init = x @ skW + skb
    k_sgemm<<<gemmGrid1, 256>>>(x, skW, xinit, n, 128, FIN, skb, nullptr);

    // ---- layer 1 (no self loops) ----
    k_sgemm<<<gemmGrid2, 256>>>(x, W1, buf1, n, 256, FIN, nullptr, nullptr);
    k_attn<<<warpGrid, 256>>>(buf1, a1s, a1d, n, 8);
    k_agg<8, false><<<warpGrid, 256>>>(buf1, b1, buf2, n);
    k_bn_elu<<<(n * 256 + 255) / 256, 256>>>(buf2, g1, be1, m1, v1, nullptr, n * 256, 255);

    // ---- layer 2 (self loops, residual) ----
    k_sgemm<<<gemmGrid2, 256>>>(buf2, W2, buf1, n, 256, 256, nullptr, nullptr);
    k_attn<<<warpGrid, 256>>>(buf1, a2s, a2d, n, 8);
    k_agg<8, true><<<warpGrid, 256>>>(buf1, b2, buf3, n);
    k_bn_elu<<<(n * 256 + 255) / 256, 256>>>(buf3, g2, be2, m2, v2, buf2, n * 256, 255);

    // ---- layer 3 (self loops, temp-scaled input folded into GEMM) ----
    k_sgemm<<<gemmGrid1, 256>>>(buf3, W3, buf1, n, 128, 256, nullptr, temp);
    k_attn<<<warpGrid, 256>>>(buf1, a3s, a3d, n, 4);
    k_agg<4, true><<<warpGrid, 256>>>(buf1, b3, buf2, n);

    // ---- final fc + log_softmax ----
    k_final<<<warpGrid, 256>>>(buf2, xinit, fcW, fcb, (float*)d_out, n);
}

// round 3
// speedup vs baseline: 1.2559x; 1.2559x over previous
#include <cuda_runtime.h>
#include <math.h>
#include <cstdint>

#define NN 50000
#define EE 800000
#define FIN 165

// ---------------- scratch (device globals; no allocation allowed) ----------------
__device__ float g_buf1[NN * 256];
__device__ float g_buf2[NN * 256];
__device__ float g_buf3[NN * 256];
__device__ float g_xinit[NN * 128];
__device__ float g_asrc[NN * 8];
__device__ float g_adst[NN * 8];
__device__ int   g_rowptr[NN + 1];
__device__ int   g_deg[NN];
__device__ int   g_col[EE];

// ---------------- CSR build (by destination) ----------------
__global__ void k_zero_deg(int n) {
    int i = blockIdx.x * blockDim.x + threadIdx.x;
    if (i < n) g_deg[i] = 0;
}
__global__ void k_count(const int* __restrict__ dst, int e) {
    int i = blockIdx.x * blockDim.x + threadIdx.x;
    if (i < e) atomicAdd(&g_deg[dst[i]], 1);
}
__global__ void k_scan(int n) {
    __shared__ int sh[1024];
    int t = threadIdx.x;
    int C = (n + 1023) / 1024;
    int base = t * C;
    int local = 0;
    for (int j = 0; j < C; j++) { int i = base + j; if (i < n) local += g_deg[i]; }
    sh[t] = local;
    __syncthreads();
    for (int off = 1; off < 1024; off <<= 1) {
        int v = (t >= off) ? sh[t - off] : 0;
        __syncthreads();
        sh[t] += v;
        __syncthreads();
    }
    int run = sh[t] - local;
    for (int j = 0; j < C; j++) { int i = base + j; if (i < n) { g_rowptr[i] = run; run += g_deg[i]; } }
    if (t == 1023) g_rowptr[n] = sh[1023];
}
__global__ void k_scatter(const int* __restrict__ src, const int* __restrict__ dst, int e) {
    int i = blockIdx.x * blockDim.x + threadIdx.x;
    if (i >= e) return;
    int d = dst[i];
    int pos = g_rowptr[d] + atomicAdd(&g_deg[d], 1);
    g_col[pos] = src[i];
}

// ================= SGEMM 128x128, BK=16, 8x8 microtile, double-buffered =================
// C[M,N] = A[M,K] @ B[K,N] (*scale) (+bias); optionally fused attention dot products:
//   asrc[r,h] = sum_d C[r, h*32+d]*a_s[h*32+d], adst likewise (computed BEFORE bias; bias
//   is only used by the skip GEMM which has ATTN=false).
// Requires N % 128 == 0. K arbitrary.
template <bool ATTN>
__global__ void __launch_bounds__(256)
k_sgemm(const float* __restrict__ A, const float* __restrict__ B, float* __restrict__ C,
        int M, int N, int K,
        const float* __restrict__ bias, const float* __restrict__ scale,
        float* __restrict__ asrc, float* __restrict__ adst,
        const float* __restrict__ a_s, const float* __restrict__ a_d, int H) {
    __shared__ __align__(16) float As[2][16][132];   // [k][m], padded row
    __shared__ __align__(16) float Bs[2][16][128];   // [k][n]

    int tid = threadIdx.x;
    int tx = tid & 15;          // 0..15 -> 8-col group
    int ty = tid >> 4;          // 0..15 -> 8-row group
    int bn = blockIdx.x * 128;
    int bm = blockIdx.y * 128;

    float acc[8][8];
#pragma unroll
    for (int i = 0; i < 8; i++)
#pragma unroll
        for (int j = 0; j < 8; j++) acc[i][j] = 0.f;

    float ar[8];
    float4 br[2];
    int nk = (K + 15) >> 4;

    // prologue: fetch tile 0 into regs
    {
#pragma unroll
        for (int j = 0; j < 8; j++) {
            int idx = tid + j * 256;
            int r = idx >> 4, k = idx & 15;
            int gr = bm + r;
            ar[j] = (gr < M && k < K) ? A[(size_t)gr * K + k] : 0.f;
        }
#pragma unroll
        for (int j = 0; j < 2; j++) {
            int k = (tid >> 5) + j * 8;
            int nn = (tid & 31) * 4;
            br[j] = (k < K) ? *(const float4*)(B + (size_t)k * N + bn + nn)
                            : make_float4(0.f, 0.f, 0.f, 0.f);
        }
    }
    // store tile 0
#pragma unroll
    for (int j = 0; j < 8; j++) {
        int idx = tid + j * 256;
        As[0][idx & 15][idx >> 4] = ar[j];
    }
#pragma unroll
    for (int j = 0; j < 2; j++) {
        int k = (tid >> 5) + j * 8;
        *(float4*)&Bs[0][k][(tid & 31) * 4] = br[j];
    }
    __syncthreads();

    for (int t = 0; t < nk; t++) {
        int cur = t & 1;
        if (t + 1 < nk) {
            int k0 = (t + 1) << 4;
#pragma unroll
            for (int j = 0; j < 8; j++) {
                int idx = tid + j * 256;
                int r = idx >> 4, k = idx & 15;
                int gr = bm + r, gk = k0 + k;
                ar[j] = (gr < M && gk < K) ? A[(size_t)gr * K + gk] : 0.f;
            }
#pragma unroll
            for (int j = 0; j < 2; j++) {
                int k = (tid >> 5) + j * 8;
                int gk = k0 + k;
                int nn = (tid & 31) * 4;
                br[j] = (gk < K) ? *(const float4*)(B + (size_t)gk * N + bn + nn)
                                 : make_float4(0.f, 0.f, 0.f, 0.f);
            }
        }
#pragma unroll
        for (int kk = 0; kk < 16; kk++) {
            float4 a0 = *(const float4*)&As[cur][kk][ty * 8];
            float4 a1 = *(const float4*)&As[cur][kk][ty * 8 + 4];
            float4 b0 = *(const float4*)&Bs[cur][kk][tx * 8];
            float4 b1 = *(const float4*)&Bs[cur][kk][tx * 8 + 4];
            float a[8] = { a0.x, a0.y, a0.z, a0.w, a1.x, a1.y, a1.z, a1.w };
            float b[8] = { b0.x, b0.y, b0.z, b0.w, b1.x, b1.y, b1.z, b1.w };
#pragma unroll
            for (int i = 0; i < 8; i++)
#pragma unroll
                for (int j = 0; j < 8; j++) acc[i][j] = fmaf(a[i], b[j], acc[i][j]);
        }
        if (t + 1 < nk) {
            __syncthreads();
            int nxt = cur ^ 1;
#pragma unroll
            for (int j = 0; j < 8; j++) {
                int idx = tid + j * 256;
                As[nxt][idx & 15][idx >> 4] = ar[j];
            }
#pragma unroll
            for (int j = 0; j < 2; j++) {
                int k = (tid >> 5) + j * 8;
                *(float4*)&Bs[nxt][k][(tid & 31) * 4] = br[j];
            }
            __syncthreads();
        }
    }

    // epilogue
    float scl = scale ? *scale : 1.0f;
    int c0 = bn + tx * 8;
#pragma unroll
    for (int i = 0; i < 8; i++) {
        int r = bm + ty * 8 + i;
        float v[8];
#pragma unroll
        for (int j = 0; j < 8; j++) {
            v[j] = acc[i][j] * scl;
            if (bias) v[j] += bias[c0 + j];
        }
        float ds = 0.f, dd = 0.f;
        if (ATTN) {
#pragma unroll
            for (int j = 0; j < 8; j++) {
                ds = fmaf(v[j], a_s[c0 + j], ds);
                dd = fmaf(v[j], a_d[c0 + j], dd);
            }
            // reduce over the 4 threads (tx%4 group) covering one 32-dim head
            ds += __shfl_xor_sync(0xffffffffu, ds, 1);
            ds += __shfl_xor_sync(0xffffffffu, ds, 2);
            dd += __shfl_xor_sync(0xffffffffu, dd, 1);
            dd += __shfl_xor_sync(0xffffffffu, dd, 2);
        }
        if (r < M) {
            *(float4*)(C + (size_t)r * N + c0)     = make_float4(v[0], v[1], v[2], v[3]);
            *(float4*)(C + (size_t)r * N + c0 + 4) = make_float4(v[4], v[5], v[6], v[7]);
            if (ATTN && (tx & 3) == 0) {
                int h = c0 >> 5;
                asrc[(size_t)r * H + h] = ds;
                adst[(size_t)r * H + h] = dd;
            }
        }
    }
}

// ---------------- GAT segment-softmax aggregation (warp per node) ----------------
// Fused: +bias, then optional BN(eval) [+resid] + ELU.
template <int H, bool SL, bool BN>
__global__ void k_agg(const float* __restrict__ h, const float* __restrict__ bias,
                      float* __restrict__ out, int n,
                      const float* __restrict__ bg, const float* __restrict__ bb,
                      const float* __restrict__ bmean, const float* __restrict__ bvar,
                      const float* __restrict__ resid) {
    const int D = H * 32;
    int w = (blockIdx.x * blockDim.x + threadIdx.x) >> 5;
    int l = threadIdx.x & 31;
    if (w >= n) return;
    int hA = l >> 3;
    float adA = g_adst[w * H + hA];
    float adB = 0.f;
    if (H == 8) adB = g_adst[w * H + 4 + hA];
    int rs = g_rowptr[w], re = g_rowptr[w + 1];

    float mxA = -1e30f, mxB = -1e30f;
    float esA = 0.f, esB = 0.f;
    if (SL) {
        float t = g_asrc[w * H + hA] + adA; esA = (t > 0.f) ? t : 0.2f * t; mxA = esA;
        if (H == 8) { float u = g_asrc[w * H + 4 + hA] + adB; esB = (u > 0.f) ? u : 0.2f * u; mxB = esB; }
    }
    for (int j = rs; j < re; j++) {
        int s = g_col[j];
        float t = g_asrc[s * H + hA] + adA; t = (t > 0.f) ? t : 0.2f * t; mxA = fmaxf(mxA, t);
        if (H == 8) { float u = g_asrc[s * H + 4 + hA] + adB; u = (u > 0.f) ? u : 0.2f * u; mxB = fmaxf(mxB, u); }
    }

    float denA = 0.f, denB = 0.f;
    float4 aA = make_float4(0.f, 0.f, 0.f, 0.f);
    float4 aB = make_float4(0.f, 0.f, 0.f, 0.f);
    if (SL) {
        float ex = __expf(esA - mxA); denA += ex;
        float4 v = *(const float4*)(h + (size_t)w * D + 4 * l);
        aA.x += ex * v.x; aA.y += ex * v.y; aA.z += ex * v.z; aA.w += ex * v.w;
        if (H == 8) {
            float ex2 = __expf(esB - mxB); denB += ex2;
            float4 u = *(const float4*)(h + (size_t)w * D + 128 + 4 * l);
            aB.x += ex2 * u.x; aB.y += ex2 * u.y; aB.z += ex2 * u.z; aB.w += ex2 * u.w;
        }
    }
    for (int j = rs; j < re; j++) {
        int s = g_col[j];
        float t = g_asrc[s * H + hA] + adA; t = (t > 0.f) ? t : 0.2f * t;
        float ex = __expf(t - mxA); denA += ex;
        float4 v = *(const float4*)(h + (size_t)s * D + 4 * l);
        aA.x += ex * v.x; aA.y += ex * v.y; aA.z += ex * v.z; aA.w += ex * v.w;
        if (H == 8) {
            float u = g_asrc[s * H + 4 + hA] + adB; u = (u > 0.f) ? u : 0.2f * u;
            float ex2 = __expf(u - mxB); denB += ex2;
            float4 q = *(const float4*)(h + (size_t)s * D + 128 + 4 * l);
            aB.x += ex2 * q.x; aB.y += ex2 * q.y; aB.z += ex2 * q.z; aB.w += ex2 * q.w;
        }
    }

    float sA = 1.f / (denA + 1e-16f);
    {
        float4 b4 = *(const float4*)(bias + 4 * l);
        float o[4] = { aA.x * sA + b4.x, aA.y * sA + b4.y, aA.z * sA + b4.z, aA.w * sA + b4.w };
        if (BN) {
            float4 gg = *(const float4*)(bg + 4 * l);
            float4 bb4 = *(const float4*)(bb + 4 * l);
            float4 mm = *(const float4*)(bmean + 4 * l);
            float4 vv = *(const float4*)(bvar + 4 * l);
            float gv[4] = { gg.x, gg.y, gg.z, gg.w }, bv[4] = { bb4.x, bb4.y, bb4.z, bb4.w };
            float mv[4] = { mm.x, mm.y, mm.z, mm.w }, vvv[4] = { vv.x, vv.y, vv.z, vv.w };
            float4 rr = resid ? *(const float4*)(resid + (size_t)w * D + 4 * l)
                              : make_float4(0.f, 0.f, 0.f, 0.f);
            float rv[4] = { rr.x, rr.y, rr.z, rr.w };
#pragma unroll
            for (int j = 0; j < 4; j++) {
                float val = (o[j] - mv[j]) * rsqrtf(vvv[j] + 1e-5f) * gv[j] + bv[j] + rv[j];
                o[j] = (val > 0.f) ? val : expm1f(val);
            }
        }
        *(float4*)(out + (size_t)w * D + 4 * l) = make_float4(o[0], o[1], o[2], o[3]);
    }
    if (H == 8) {
        float sB = 1.f / (denB + 1e-16f);
        float4 b4 = *(const float4*)(bias + 128 + 4 * l);
        float o[4] = { aB.x * sB + b4.x, aB.y * sB + b4.y, aB.z * sB + b4.z, aB.w * sB + b4.w };
        if (BN) {
            int d0 = 128 + 4 * l;
            float4 gg = *(const float4*)(bg + d0);
            float4 bb4 = *(const float4*)(bb + d0);
            float4 mm = *(const float4*)(bmean + d0);
            float4 vv = *(const float4*)(bvar + d0);
            float gv[4] = { gg.x, gg.y, gg.z, gg.w }, bv[4] = { bb4.x, bb4.y, bb4.z, bb4.w };
            float mv[4] = { mm.x, mm.y, mm.z, mm.w }, vvv[4] = { vv.x, vv.y, vv.z, vv.w };
            float4 rr = resid ? *(const float4*)(resid + (size_t)w * D + d0)
                              : make_float4(0.f, 0.f, 0.f, 0.f);
            float rv[4] = { rr.x, rr.y, rr.z, rr.w };
#pragma unroll
            for (int j = 0; j < 4; j++) {
                float val = (o[j] - mv[j]) * rsqrtf(vvv[j] + 1e-5f) * gv[j] + bv[j] + rv[j];
                o[j] = (val > 0.f) ? val : expm1f(val);
            }
        }
        *(float4*)(out + (size_t)w * D + 128 + 4 * l) = make_float4(o[0], o[1], o[2], o[3]);
    }
}

// ---------------- final: (h3 + x_init) @ fcW + fcb, log_softmax ----------------
__global__ void k_final(const float* __restrict__ h3, const float* __restrict__ xi,
                        const float* __restrict__ fcW, const float* __restrict__ fcb,
                        float* __restrict__ out, int n) {
    int w = (blockIdx.x * blockDim.x + threadIdx.x) >> 5;
    int l = threadIdx.x & 31;
    if (w >= n) return;
    float4 a = *(const float4*)(h3 + (size_t)w * 128 + 4 * l);
    float4 b = *(const float4*)(xi + (size_t)w * 128 + 4 * l);
    float v0 = a.x + b.x, v1 = a.y + b.y, v2 = a.z + b.z, v3 = a.w + b.w;
    int d = 4 * l;
    float z0 = v0 * fcW[d * 2]     + v1 * fcW[(d + 1) * 2]     + v2 * fcW[(d + 2) * 2]     + v3 * fcW[(d + 3) * 2];
    float z1 = v0 * fcW[d * 2 + 1] + v1 * fcW[(d + 1) * 2 + 1] + v2 * fcW[(d + 2) * 2 + 1] + v3 * fcW[(d + 3) * 2 + 1];
#pragma unroll
    for (int o = 16; o; o >>= 1) {
        z0 += __shfl_down_sync(0xffffffffu, z0, o);
        z1 += __shfl_down_sync(0xffffffffu, z1, o);
    }
    if (l == 0) {
        z0 += fcb[0]; z1 += fcb[1];
        float mx = fmaxf(z0, z1);
        float lse = mx + logf(expf(z0 - mx) + expf(z1 - mx));
        out[w * 2] = z0 - lse;
        out[w * 2 + 1] = z1 - lse;
    }
}

// ---------------- launch ----------------
extern "C" void kernel_launch(void* const* d_in, const int* in_sizes, int n_in,
                              void* d_out, int out_size) {
    const float* x   = (const float*)d_in[0];
    const int*   ei  = (const int*)d_in[1];
    const float* W1  = (const float*)d_in[2];
    const float* a1s = (const float*)d_in[3];
    const float* a1d = (const float*)d_in[4];
    const float* b1  = (const float*)d_in[5];
    const float* g1  = (const float*)d_in[6];
    const float* be1 = (const float*)d_in[7];
    const float* m1  = (const float*)d_in[8];
    const float* v1  = (const float*)d_in[9];
    const float* W2  = (const float*)d_in[10];
    const float* a2s = (const float*)d_in[11];
    const float* a2d = (const float*)d_in[12];
    const float* b2  = (const float*)d_in[13];
    const float* g2  = (const float*)d_in[14];
    const float* be2 = (const float*)d_in[15];
    const float* m2  = (const float*)d_in[16];
    const float* v2  = (const float*)d_in[17];
    const float* W3  = (const float*)d_in[18];
    const float* a3s = (const float*)d_in[19];
    const float* a3d = (const float*)d_in[20];
    const float* b3  = (const float*)d_in[21];
    const float* fcW = (const float*)d_in[22];
    const float* fcb = (const float*)d_in[23];
    const float* skW = (const float*)d_in[24];
    const float* skb = (const float*)d_in[25];
    const float* temp = (const float*)d_in[26];

    int n = in_sizes[0] / FIN;   // 50000
    int e = in_sizes[1] / 2;     // 800000
    const int* src = ei;
    const int* dst = ei + e;

    float *buf1, *buf2, *buf3, *xinit, *asrc, *adst;
    cudaGetSymbolAddress((void**)&buf1, g_buf1);
    cudaGetSymbolAddress((void**)&buf2, g_buf2);
    cudaGetSymbolAddress((void**)&buf3, g_buf3);
    cudaGetSymbolAddress((void**)&xinit, g_xinit);
    cudaGetSymbolAddress((void**)&asrc, g_asrc);
    cudaGetSymbolAddress((void**)&adst, g_adst);

    int nb256 = (n + 255) / 256;
    int eb256 = (e + 255) / 256;
    int warpGrid = (n * 32 + 255) / 256;
    int gm = (n + 127) / 128;

    // CSR build (by destination)
    k_zero_deg<<<nb256, 256>>>(n);
    k_count<<<eb256, 256>>>(dst, e);
    k_scan<<<1, 1024>>>(n);
    k_zero_deg<<<nb256, 256>>>(n);
    k_scatter<<<eb256, 256>>>(src, dst, e);

    // skip connection: x_init = x @ skW + skb
    k_sgemm<false><<<dim3(1, gm), 256>>>(x, skW, xinit, n, 128, FIN, skb, nullptr,
                                         nullptr, nullptr, nullptr, nullptr, 4);

    // ---- layer 1 (no self loops) ----
    k_sgemm<true><<<dim3(2, gm), 256>>>(x, W1, buf1, n, 256, FIN, nullptr, nullptr,
                                        asrc, adst, a1s, a1d, 8);
    k_agg<8, false, true><<<warpGrid, 256>>>(buf1, b1, buf2, n, g1, be1, m1, v1, nullptr);

    // ---- layer 2 (self loops, residual) ----
    k_sgemm<true><<<dim3(2, gm), 256>>>(buf2, W2, buf1, n, 256, 256, nullptr, nullptr,
                                        asrc, adst, a2s, a2d, 8);
    k_agg<8, true, true><<<warpGrid, 256>>>(buf1, b2, buf3, n, g2, be2, m2, v2, buf2);

    // ---- layer 3 (self loops, temp folded into GEMM scale) ----
    k_sgemm<true><<<dim3(1, gm), 256>>>(buf3, W3, buf1, n, 128, 256, nullptr, temp,
                                        asrc, adst, a3s, a3d, 4);
    k_agg<4, true, false><<<warpGrid, 256>>>(buf1, b3, buf2, n, nullptr, nullptr, nullptr, nullptr, nullptr);

    // ---- final fc + log_softmax ----
    k_final<<<warpGrid, 256>>>(buf2, xinit, fcW, fcb, (float*)d_out, n);
}

// round 4
// speedup vs baseline: 1.2793x; 1.0186x over previous
#include <cuda_runtime.h>
#include <math.h>
#include <cstdint>

#define NN 50000
#define EE 800000
#define FIN 165

// ---------------- scratch (device globals; no allocation allowed) ----------------
__device__ float g_buf1[NN * 256];
__device__ float g_buf2[NN * 256];
__device__ float g_buf3[NN * 256];
__device__ float g_xinit[NN * 128];
__device__ float g_asrc[NN * 8];
__device__ float g_adst[NN * 8];
__device__ int   g_rowptr[NN + 1];
__device__ int   g_cursor[NN];
__device__ int   g_col[EE];

// ---------------- CSR build (by destination) ----------------
__global__ void k_zero(int n) {
    int i = blockIdx.x * blockDim.x + threadIdx.x;
    if (i < n) g_cursor[i] = 0;
}
__global__ void k_count(const int* __restrict__ dst, int e) {
    int i = blockIdx.x * blockDim.x + threadIdx.x;
    if (i < e) atomicAdd(&g_cursor[dst[i]], 1);
}
// exclusive scan of g_cursor -> g_rowptr, and reset g_cursor to the row starts
__global__ void k_scan(int n) {
    __shared__ int sh[1024];
    int t = threadIdx.x;
    int C = (n + 1023) / 1024;
    int base = t * C;
    int local = 0;
    for (int j = 0; j < C; j++) { int i = base + j; if (i < n) local += g_cursor[i]; }
    sh[t] = local;
    __syncthreads();
    for (int off = 1; off < 1024; off <<= 1) {
        int v = (t >= off) ? sh[t - off] : 0;
        __syncthreads();
        sh[t] += v;
        __syncthreads();
    }
    int run = sh[t] - local;
    for (int j = 0; j < C; j++) {
        int i = base + j;
        if (i < n) { int d = g_cursor[i]; g_rowptr[i] = run; g_cursor[i] = run; run += d; }
    }
    if (t == 1023) g_rowptr[n] = sh[1023];
}
__global__ void k_scatter(const int* __restrict__ src, const int* __restrict__ dst, int e) {
    int i = blockIdx.x * blockDim.x + threadIdx.x;
    if (i >= e) return;
    int pos = atomicAdd(&g_cursor[dst[i]], 1);
    g_col[pos] = src[i];
}

// ================= SGEMM 128x128, BK=16, 8x8 microtile, double-buffered =================
// C[M,N] = A[M,K] @ B[K,N] (*scale) (+bias); optionally fused attention dot products.
template <bool ATTN>
__global__ void __launch_bounds__(256)
k_sgemm(const float* __restrict__ A, const float* __restrict__ B, float* __restrict__ C,
        int M, int N, int K,
        const float* __restrict__ bias, const float* __restrict__ scale,
        float* __restrict__ asrc, float* __restrict__ adst,
        const float* __restrict__ a_s, const float* __restrict__ a_d, int H) {
    __shared__ __align__(16) float As[2][16][132];
    __shared__ __align__(16) float Bs[2][16][128];

    int tid = threadIdx.x;
    int tx = tid & 15;
    int ty = tid >> 4;
    int bn = blockIdx.x * 128;
    int bm = blockIdx.y * 128;

    float acc[8][8];
#pragma unroll
    for (int i = 0; i < 8; i++)
#pragma unroll
        for (int j = 0; j < 8; j++) acc[i][j] = 0.f;

    float ar[8];
    float4 br[2];
    int nk = (K + 15) >> 4;

    {
#pragma unroll
        for (int j = 0; j < 8; j++) {
            int idx = tid + j * 256;
            int r = idx >> 4, k = idx & 15;
            int gr = bm + r;
            ar[j] = (gr < M && k < K) ? A[(size_t)gr * K + k] : 0.f;
        }
#pragma unroll
        for (int j = 0; j < 2; j++) {
            int k = (tid >> 5) + j * 8;
            int nn = (tid & 31) * 4;
            br[j] = (k < K) ? *(const float4*)(B + (size_t)k * N + bn + nn)
                            : make_float4(0.f, 0.f, 0.f, 0.f);
        }
    }
#pragma unroll
    for (int j = 0; j < 8; j++) {
        int idx = tid + j * 256;
        As[0][idx & 15][idx >> 4] = ar[j];
    }
#pragma unroll
    for (int j = 0; j < 2; j++) {
        int k = (tid >> 5) + j * 8;
        *(float4*)&Bs[0][k][(tid & 31) * 4] = br[j];
    }
    __syncthreads();

    for (int t = 0; t < nk; t++) {
        int cur = t & 1;
        if (t + 1 < nk) {
            int k0 = (t + 1) << 4;
#pragma unroll
            for (int j = 0; j < 8; j++) {
                int idx = tid + j * 256;
                int r = idx >> 4, k = idx & 15;
                int gr = bm + r, gk = k0 + k;
                ar[j] = (gr < M && gk < K) ? A[(size_t)gr * K + gk] : 0.f;
            }
#pragma unroll
            for (int j = 0; j < 2; j++) {
                int k = (tid >> 5) + j * 8;
                int gk = k0 + k;
                int nn = (tid & 31) * 4;
                br[j] = (gk < K) ? *(const float4*)(B + (size_t)gk * N + bn + nn)
                                 : make_float4(0.f, 0.f, 0.f, 0.f);
            }
        }
#pragma unroll
        for (int kk = 0; kk < 16; kk++) {
            float4 a0 = *(const float4*)&As[cur][kk][ty * 8];
            float4 a1 = *(const float4*)&As[cur][kk][ty * 8 + 4];
            float4 b0 = *(const float4*)&Bs[cur][kk][tx * 8];
            float4 b1 = *(const float4*)&Bs[cur][kk][tx * 8 + 4];
            float a[8] = { a0.x, a0.y, a0.z, a0.w, a1.x, a1.y, a1.z, a1.w };
            float b[8] = { b0.x, b0.y, b0.z, b0.w, b1.x, b1.y, b1.z, b1.w };
#pragma unroll
            for (int i = 0; i < 8; i++)
#pragma unroll
                for (int j = 0; j < 8; j++) acc[i][j] = fmaf(a[i], b[j], acc[i][j]);
        }
        if (t + 1 < nk) {
            __syncthreads();
            int nxt = cur ^ 1;
#pragma unroll
            for (int j = 0; j < 8; j++) {
                int idx = tid + j * 256;
                As[nxt][idx & 15][idx >> 4] = ar[j];
            }
#pragma unroll
            for (int j = 0; j < 2; j++) {
                int k = (tid >> 5) + j * 8;
                *(float4*)&Bs[nxt][k][(tid & 31) * 4] = br[j];
            }
            __syncthreads();
        }
    }

    float scl = scale ? *scale : 1.0f;
    int c0 = bn + tx * 8;
#pragma unroll
    for (int i = 0; i < 8; i++) {
        int r = bm + ty * 8 + i;
        float v[8];
#pragma unroll
        for (int j = 0; j < 8; j++) {
            v[j] = acc[i][j] * scl;
            if (bias) v[j] += bias[c0 + j];
        }
        float ds = 0.f, dd = 0.f;
        if (ATTN) {
#pragma unroll
            for (int j = 0; j < 8; j++) {
                ds = fmaf(v[j], a_s[c0 + j], ds);
                dd = fmaf(v[j], a_d[c0 + j], dd);
            }
            ds += __shfl_xor_sync(0xffffffffu, ds, 1);
            ds += __shfl_xor_sync(0xffffffffu, ds, 2);
            dd += __shfl_xor_sync(0xffffffffu, dd, 1);
            dd += __shfl_xor_sync(0xffffffffu, dd, 2);
        }
        if (r < M) {
            *(float4*)(C + (size_t)r * N + c0)     = make_float4(v[0], v[1], v[2], v[3]);
            *(float4*)(C + (size_t)r * N + c0 + 4) = make_float4(v[4], v[5], v[6], v[7]);
            if (ATTN && (tx & 3) == 0) {
                int h = c0 >> 5;
                asrc[(size_t)r * H + h] = ds;
                adst[(size_t)r * H + h] = dd;
            }
        }
    }
}

// ---------------- GAT aggregation: single pass (no max-subtract), warp per (node, half) ----
// HALVES=2 for H=8 (each warp: 128 dims + 4 heads), 1 for H=4.
// Fused epilogue: +bias, optional BN [+resid] + ELU, or FINAL (=+x_init, @fcW+fcb, log_softmax).
template <int H, bool SL, bool BN, bool FINAL>
__global__ void k_agg(const float* __restrict__ h, const float* __restrict__ bias,
                      float* __restrict__ out, int n,
                      const float* __restrict__ bg, const float* __restrict__ bb,
                      const float* __restrict__ bmean, const float* __restrict__ bvar,
                      const float* __restrict__ resid,
                      const float* __restrict__ xi, const float* __restrict__ fcW,
                      const float* __restrict__ fcb, float* __restrict__ fout) {
    const int D = H * 32;
    constexpr int SHIFT = (H == 8) ? 1 : 0;
    int gw = (blockIdx.x * blockDim.x + threadIdx.x) >> 5;
    int l = threadIdx.x & 31;
    int node = gw >> SHIFT;
    int half = (H == 8) ? (gw & 1) : 0;
    if (node >= n) return;

    int myhead = half * 4 + (l >> 3);
    int d0 = half * 128 + 4 * l;             // dim offset within D
    float ad = g_adst[node * H + myhead];
    int rs = g_rowptr[node], re = g_rowptr[node + 1];

    float den = 0.f;
    float4 acc = make_float4(0.f, 0.f, 0.f, 0.f);
    if (SL) {
        float t = g_asrc[node * H + myhead] + ad;
        t = (t > 0.f) ? t : 0.2f * t;
        float ex = __expf(t);
        den += ex;
        float4 v = *(const float4*)(h + (size_t)node * D + d0);
        acc.x += ex * v.x; acc.y += ex * v.y; acc.z += ex * v.z; acc.w += ex * v.w;
    }
    for (int j = rs; j < re; j++) {
        int s = g_col[j];
        float t = g_asrc[s * H + myhead] + ad;
        t = (t > 0.f) ? t : 0.2f * t;
        float ex = __expf(t);
        den += ex;
        float4 v = *(const float4*)(h + (size_t)s * D + d0);
        acc.x += ex * v.x; acc.y += ex * v.y; acc.z += ex * v.z; acc.w += ex * v.w;
    }

    float inv = 1.f / (den + 1e-16f);
    float4 b4 = *(const float4*)(bias + d0);
    float o[4] = { acc.x * inv + b4.x, acc.y * inv + b4.y, acc.z * inv + b4.z, acc.w * inv + b4.w };

    if (BN) {
        float4 gg = *(const float4*)(bg + d0);
        float4 bbv = *(const float4*)(bb + d0);
        float4 mm = *(const float4*)(bmean + d0);
        float4 vv = *(const float4*)(bvar + d0);
        float gvx[4] = { gg.x, gg.y, gg.z, gg.w }, bvx[4] = { bbv.x, bbv.y, bbv.z, bbv.w };
        float mvx[4] = { mm.x, mm.y, mm.z, mm.w }, vvx[4] = { vv.x, vv.y, vv.z, vv.w };
        float rv[4] = { 0.f, 0.f, 0.f, 0.f };
        if (resid) {
            float4 rr = *(const float4*)(resid + (size_t)node * D + d0);
            rv[0] = rr.x; rv[1] = rr.y; rv[2] = rr.z; rv[3] = rr.w;
        }
#pragma unroll
        for (int j = 0; j < 4; j++) {
            float val = (o[j] - mvx[j]) * rsqrtf(vvx[j] + 1e-5f) * gvx[j] + bvx[j] + rv[j];
            o[j] = (val > 0.f) ? val : expm1f(val);
        }
    }

    if (!FINAL) {
        *(float4*)(out + (size_t)node * D + d0) = make_float4(o[0], o[1], o[2], o[3]);
    } else {
        // (o + x_init) @ fcW + fcb, log_softmax; D == 128, one warp covers all dims
        float4 x4 = *(const float4*)(xi + (size_t)node * 128 + 4 * l);
        float v[4] = { o[0] + x4.x, o[1] + x4.y, o[2] + x4.z, o[3] + x4.w };
        int d = 4 * l;
        float z0 = 0.f, z1 = 0.f;
#pragma unroll
        for (int j = 0; j < 4; j++) {
            z0 = fmaf(v[j], fcW[(d + j) * 2], z0);
            z1 = fmaf(v[j], fcW[(d + j) * 2 + 1], z1);
        }
#pragma unroll
        for (int off = 16; off; off >>= 1) {
            z0 += __shfl_down_sync(0xffffffffu, z0, off);
            z1 += __shfl_down_sync(0xffffffffu, z1, off);
        }
        if (l == 0) {
            z0 += fcb[0]; z1 += fcb[1];
            float mx = fmaxf(z0, z1);
            float lse = mx + logf(expf(z0 - mx) + expf(z1 - mx));
            fout[node * 2] = z0 - lse;
            fout[node * 2 + 1] = z1 - lse;
        }
    }
}

// ---------------- launch ----------------
extern "C" void kernel_launch(void* const* d_in, const int* in_sizes, int n_in,
                              void* d_out, int out_size) {
    const float* x   = (const float*)d_in[0];
    const int*   ei  = (const int*)d_in[1];
    const float* W1  = (const float*)d_in[2];
    const float* a1s = (const float*)d_in[3];
    const float* a1d = (const float*)d_in[4];
    const float* b1  = (const float*)d_in[5];
    const float* g1  = (const float*)d_in[6];
    const float* be1 = (const float*)d_in[7];
    const float* m1  = (const float*)d_in[8];
    const float* v1  = (const float*)d_in[9];
    const float* W2  = (const float*)d_in[10];
    const float* a2s = (const float*)d_in[11];
    const float* a2d = (const float*)d_in[12];
    const float* b2  = (const float*)d_in[13];
    const float* g2  = (const float*)d_in[14];
    const float* be2 = (const float*)d_in[15];
    const float* m2  = (const float*)d_in[16];
    const float* v2  = (const float*)d_in[17];
    const float* W3  = (const float*)d_in[18];
    const float* a3s = (const float*)d_in[19];
    const float* a3d = (const float*)d_in[20];
    const float* b3  = (const float*)d_in[21];
    const float* fcW = (const float*)d_in[22];
    const float* fcb = (const float*)d_in[23];
    const float* skW = (const float*)d_in[24];
    const float* skb = (const float*)d_in[25];
    const float* temp = (const float*)d_in[26];

    int n = in_sizes[0] / FIN;   // 50000
    int e = in_sizes[1] / 2;     // 800000
    const int* src = ei;
    const int* dst = ei + e;

    float *buf1, *buf2, *buf3, *xinit, *asrc, *adst;
    cudaGetSymbolAddress((void**)&buf1, g_buf1);
    cudaGetSymbolAddress((void**)&buf2, g_buf2);
    cudaGetSymbolAddress((void**)&buf3, g_buf3);
    cudaGetSymbolAddress((void**)&xinit, g_xinit);
    cudaGetSymbolAddress((void**)&asrc, g_asrc);
    cudaGetSymbolAddress((void**)&adst, g_adst);

    int nb256 = (n + 255) / 256;
    int eb256 = (e + 255) / 256;
    int wg1 = (n * 32 + 255) / 256;       // 1 warp/node
    int wg2 = (n * 64 + 255) / 256;       // 2 warps/node
    int gm = (n + 127) / 128;

    // CSR build (by destination)
    k_zero<<<nb256, 256>>>(n);
    k_count<<<eb256, 256>>>(dst, e);
    k_scan<<<1, 1024>>>(n);
    k_scatter<<<eb256, 256>>>(src, dst, e);

    // skip connection: x_init = x @ skW + skb
    k_sgemm<false><<<dim3(1, gm), 256>>>(x, skW, xinit, n, 128, FIN, skb, nullptr,
                                         nullptr, nullptr, nullptr, nullptr, 4);

    // ---- layer 1 (no self loops) ----
    k_sgemm<true><<<dim3(2, gm), 256>>>(x, W1, buf1, n, 256, FIN, nullptr, nullptr,
                                        asrc, adst, a1s, a1d, 8);
    k_agg<8, false, true, false><<<wg2, 256>>>(buf1, b1, buf2, n, g1, be1, m1, v1, nullptr,
                                               nullptr, nullptr, nullptr, nullptr);

    // ---- layer 2 (self loops, residual) ----
    k_sgemm<true><<<dim3(2, gm), 256>>>(buf2, W2, buf1, n, 256, 256, nullptr, nullptr,
                                        asrc, adst, a2s, a2d, 8);
    k_agg<8, true, true, false><<<wg2, 256>>>(buf1, b2, buf3, n, g2, be2, m2, v2, buf2,
                                              nullptr, nullptr, nullptr, nullptr);

    // ---- layer 3 (self loops, temp folded into GEMM scale), fused final ----
    k_sgemm<true><<<dim3(1, gm), 256>>>(buf3, W3, buf1, n, 128, 256, nullptr, temp,
                                        asrc, adst, a3s, a3d, 4);
    k_agg<4, true, false, true><<<wg1, 256>>>(buf1, b3, nullptr, n, nullptr, nullptr, nullptr,
                                              nullptr, nullptr, xinit, fcW, fcb, (float*)d_out);
}

// round 5
// speedup vs baseline: 1.3415x; 1.0486x over previous
#include <cuda_runtime.h>
#include <math.h>
#include <cstdint>

#define NN 50000
#define EE 800000
#define FIN 165

// ---------------- scratch (device globals; no allocation allowed) ----------------
__device__ float g_buf1[NN * 256];
__device__ float g_buf2[NN * 256];
__device__ float g_buf3[NN * 256];
__device__ float g_xinit[NN * 128];
__device__ float g_asrc[NN * 8];
__device__ float g_adst[NN * 8];
__device__ int   g_rowptr[NN + 1];
__device__ int   g_cursor[NN];
__device__ int   g_col[EE];

// ---------------- packed f32x2 helpers ----------------
__device__ __forceinline__ unsigned long long pack2(float lo, float hi) {
    unsigned long long r;
    asm("mov.b64 %0, {%1, %2};" : "=l"(r)
        : "r"(__float_as_uint(lo)), "r"(__float_as_uint(hi)));
    return r;
}
__device__ __forceinline__ float2 unpack2(unsigned long long v) {
    unsigned int lo, hi;
    asm("mov.b64 {%0, %1}, %2;" : "=r"(lo), "=r"(hi) : "l"(v));
    return make_float2(__uint_as_float(lo), __uint_as_float(hi));
}
#define FFMA2(acc, a, b) \
    asm("fma.rn.f32x2 %0, %1, %2, %0;" : "+l"(acc) : "l"(a), "l"(b))

// ---------------- CSR build (by destination) ----------------
__global__ void k_zero(int n) {
    int i = blockIdx.x * blockDim.x + threadIdx.x;
    if (i < n) g_cursor[i] = 0;
}
__global__ void k_count(const int* __restrict__ dst, int e) {
    int i = blockIdx.x * blockDim.x + threadIdx.x;
    if (i < e) atomicAdd(&g_cursor[dst[i]], 1);
}
__global__ void k_scan(int n) {
    __shared__ int sh[1024];
    int t = threadIdx.x;
    int C = (n + 1023) / 1024;
    int base = t * C;
    int local = 0;
    for (int j = 0; j < C; j++) { int i = base + j; if (i < n) local += g_cursor[i]; }
    sh[t] = local;
    __syncthreads();
    for (int off = 1; off < 1024; off <<= 1) {
        int v = (t >= off) ? sh[t - off] : 0;
        __syncthreads();
        sh[t] += v;
        __syncthreads();
    }
    int run = sh[t] - local;
    for (int j = 0; j < C; j++) {
        int i = base + j;
        if (i < n) { int d = g_cursor[i]; g_rowptr[i] = run; g_cursor[i] = run; run += d; }
    }
    if (t == 1023) g_rowptr[n] = sh[1023];
}
__global__ void k_scatter(const int* __restrict__ src, const int* __restrict__ dst, int e) {
    int i = blockIdx.x * blockDim.x + threadIdx.x;
    if (i >= e) return;
    int pos = atomicAdd(&g_cursor[dst[i]], 1);
    g_col[pos] = src[i];
}

// ================= SGEMM 128x128, BK=16, 8x8 microtile, FFMA2 packed, double-buffered ======
// C[M,N] = A[M,K] @ B[K,N] (*scale) (+bias); optionally fused attention dot products.
template <bool ATTN>
__global__ void __launch_bounds__(256)
k_sgemm(const float* __restrict__ A, const float* __restrict__ B, float* __restrict__ C,
        int M, int N, int K,
        const float* __restrict__ bias, const float* __restrict__ scale,
        float* __restrict__ asrc, float* __restrict__ adst,
        const float* __restrict__ a_s, const float* __restrict__ a_d, int H) {
    __shared__ __align__(16) float As[2][16][132];
    __shared__ __align__(16) float Bs[2][16][128];

    int tid = threadIdx.x;
    int tx = tid & 15;
    int ty = tid >> 4;
    int bn = blockIdx.x * 128;
    int bm = blockIdx.y * 128;

    // packed accumulators: acc2[i2][j] = (row 2*i2, row 2*i2+1) x col j
    unsigned long long acc2[4][8];
#pragma unroll
    for (int i = 0; i < 4; i++)
#pragma unroll
        for (int j = 0; j < 8; j++) acc2[i][j] = 0ull;

    float ar[8];
    float4 br[2];
    int nk = (K + 15) >> 4;

    {
#pragma unroll
        for (int j = 0; j < 8; j++) {
            int idx = tid + j * 256;
            int r = idx >> 4, k = idx & 15;
            int gr = bm + r;
            ar[j] = (gr < M && k < K) ? A[(size_t)gr * K + k] : 0.f;
        }
#pragma unroll
        for (int j = 0; j < 2; j++) {
            int k = (tid >> 5) + j * 8;
            int nn = (tid & 31) * 4;
            br[j] = (k < K) ? *(const float4*)(B + (size_t)k * N + bn + nn)
                            : make_float4(0.f, 0.f, 0.f, 0.f);
        }
    }
#pragma unroll
    for (int j = 0; j < 8; j++) {
        int idx = tid + j * 256;
        As[0][idx & 15][idx >> 4] = ar[j];
    }
#pragma unroll
    for (int j = 0; j < 2; j++) {
        int k = (tid >> 5) + j * 8;
        *(float4*)&Bs[0][k][(tid & 31) * 4] = br[j];
    }
    __syncthreads();

    for (int t = 0; t < nk; t++) {
        int cur = t & 1;
        if (t + 1 < nk) {
            int k0 = (t + 1) << 4;
#pragma unroll
            for (int j = 0; j < 8; j++) {
                int idx = tid + j * 256;
                int r = idx >> 4, k = idx & 15;
                int gr = bm + r, gk = k0 + k;
                ar[j] = (gr < M && gk < K) ? A[(size_t)gr * K + gk] : 0.f;
            }
#pragma unroll
            for (int j = 0; j < 2; j++) {
                int k = (tid >> 5) + j * 8;
                int gk = k0 + k;
                int nn = (tid & 31) * 4;
                br[j] = (gk < K) ? *(const float4*)(B + (size_t)gk * N + bn + nn)
                                 : make_float4(0.f, 0.f, 0.f, 0.f);
            }
        }
#pragma unroll
        for (int kk = 0; kk < 16; kk++) {
            float4 a0 = *(const float4*)&As[cur][kk][ty * 8];
            float4 a1 = *(const float4*)&As[cur][kk][ty * 8 + 4];
            float4 b0 = *(const float4*)&Bs[cur][kk][tx * 8];
            float4 b1 = *(const float4*)&Bs[cur][kk][tx * 8 + 4];
            unsigned long long a2[4];
            a2[0] = pack2(a0.x, a0.y);
            a2[1] = pack2(a0.z, a0.w);
            a2[2] = pack2(a1.x, a1.y);
            a2[3] = pack2(a1.z, a1.w);
            unsigned long long bb[8];
            bb[0] = pack2(b0.x, b0.x); bb[1] = pack2(b0.y, b0.y);
            bb[2] = pack2(b0.z, b0.z); bb[3] = pack2(b0.w, b0.w);
            bb[4] = pack2(b1.x, b1.x); bb[5] = pack2(b1.y, b1.y);
            bb[6] = pack2(b1.z, b1.z); bb[7] = pack2(b1.w, b1.w);
#pragma unroll
            for (int i2 = 0; i2 < 4; i2++)
#pragma unroll
                for (int j = 0; j < 8; j++) FFMA2(acc2[i2][j], a2[i2], bb[j]);
        }
        if (t + 1 < nk) {
            __syncthreads();
            int nxt = cur ^ 1;
#pragma unroll
            for (int j = 0; j < 8; j++) {
                int idx = tid + j * 256;
                As[nxt][idx & 15][idx >> 4] = ar[j];
            }
#pragma unroll
            for (int j = 0; j < 2; j++) {
                int k = (tid >> 5) + j * 8;
                *(float4*)&Bs[nxt][k][(tid & 31) * 4] = br[j];
            }
            __syncthreads();
        }
    }

    float scl = scale ? *scale : 1.0f;
    int c0 = bn + tx * 8;
#pragma unroll
    for (int i2 = 0; i2 < 4; i2++) {
        float2 cp[8];
#pragma unroll
        for (int j = 0; j < 8; j++) cp[j] = unpack2(acc2[i2][j]);
#pragma unroll
        for (int part = 0; part < 2; part++) {
            int r = bm + ty * 8 + i2 * 2 + part;
            float v[8];
#pragma unroll
            for (int j = 0; j < 8; j++) {
                v[j] = (part ? cp[j].y : cp[j].x) * scl;
                if (bias) v[j] += bias[c0 + j];
            }
            float ds = 0.f, dd = 0.f;
            if (ATTN) {
#pragma unroll
                for (int j = 0; j < 8; j++) {
                    ds = fmaf(v[j], a_s[c0 + j], ds);
                    dd = fmaf(v[j], a_d[c0 + j], dd);
                }
                ds += __shfl_xor_sync(0xffffffffu, ds, 1);
                ds += __shfl_xor_sync(0xffffffffu, ds, 2);
                dd += __shfl_xor_sync(0xffffffffu, dd, 1);
                dd += __shfl_xor_sync(0xffffffffu, dd, 2);
            }
            if (r < M) {
                *(float4*)(C + (size_t)r * N + c0)     = make_float4(v[0], v[1], v[2], v[3]);
                *(float4*)(C + (size_t)r * N + c0 + 4) = make_float4(v[4], v[5], v[6], v[7]);
                if (ATTN && (tx & 3) == 0) {
                    int h = c0 >> 5;
                    asrc[(size_t)r * H + h] = ds;
                    adst[(size_t)r * H + h] = dd;
                }
            }
        }
    }
}

// ---------------- GAT aggregation: single pass, warp per (node, half), 2x unrolled ----------
template <int H, bool SL, bool BN, bool FINAL>
__global__ void k_agg(const float* __restrict__ h, const float* __restrict__ bias,
                      float* __restrict__ out, int n,
                      const float* __restrict__ bg, const float* __restrict__ bb,
                      const float* __restrict__ bmean, const float* __restrict__ bvar,
                      const float* __restrict__ resid,
                      const float* __restrict__ xi, const float* __restrict__ fcW,
                      const float* __restrict__ fcb, float* __restrict__ fout) {
    const int D = H * 32;
    constexpr int SHIFT = (H == 8) ? 1 : 0;
    int gw = (blockIdx.x * blockDim.x + threadIdx.x) >> 5;
    int l = threadIdx.x & 31;
    int node = gw >> SHIFT;
    int half = (H == 8) ? (gw & 1) : 0;
    if (node >= n) return;

    int myhead = half * 4 + (l >> 3);
    int d0 = half * 128 + 4 * l;
    float ad = g_adst[node * H + myhead];
    int rs = g_rowptr[node], re = g_rowptr[node + 1];

    float den = 0.f;
    float4 acc = make_float4(0.f, 0.f, 0.f, 0.f);
    if (SL) {
        float t = g_asrc[node * H + myhead] + ad;
        t = (t > 0.f) ? t : 0.2f * t;
        float ex = __expf(t);
        den += ex;
        float4 v = *(const float4*)(h + (size_t)node * D + d0);
        acc.x += ex * v.x; acc.y += ex * v.y; acc.z += ex * v.z; acc.w += ex * v.w;
    }
    int j = rs;
    for (; j + 1 < re; j += 2) {
        int s0 = g_col[j];
        int s1 = g_col[j + 1];
        float t0 = g_asrc[s0 * H + myhead] + ad;
        float t1 = g_asrc[s1 * H + myhead] + ad;
        t0 = (t0 > 0.f) ? t0 : 0.2f * t0;
        t1 = (t1 > 0.f) ? t1 : 0.2f * t1;
        float e0 = __expf(t0);
        float e1 = __expf(t1);
        float4 v0 = *(const float4*)(h + (size_t)s0 * D + d0);
        float4 v1 = *(const float4*)(h + (size_t)s1 * D + d0);
        den += e0 + e1;
        acc.x += e0 * v0.x + e1 * v1.x;
        acc.y += e0 * v0.y + e1 * v1.y;
        acc.z += e0 * v0.z + e1 * v1.z;
        acc.w += e0 * v0.w + e1 * v1.w;
    }
    if (j < re) {
        int s = g_col[j];
        float t = g_asrc[s * H + myhead] + ad;
        t = (t > 0.f) ? t : 0.2f * t;
        float ex = __expf(t);
        den += ex;
        float4 v = *(const float4*)(h + (size_t)s * D + d0);
        acc.x += ex * v.x; acc.y += ex * v.y; acc.z += ex * v.z; acc.w += ex * v.w;
    }

    float inv = 1.f / (den + 1e-16f);
    float4 b4 = *(const float4*)(bias + d0);
    float o[4] = { acc.x * inv + b4.x, acc.y * inv + b4.y, acc.z * inv + b4.z, acc.w * inv + b4.w };

    if (BN) {
        float4 gg = *(const float4*)(bg + d0);
        float4 bbv = *(const float4*)(bb + d0);
        float4 mm = *(const float4*)(bmean + d0);
        float4 vv = *(const float4*)(bvar + d0);
        float gvx[4] = { gg.x, gg.y, gg.z, gg.w }, bvx[4] = { bbv.x, bbv.y, bbv.z, bbv.w };
        float mvx[4] = { mm.x, mm.y, mm.z, mm.w }, vvx[4] = { vv.x, vv.y, vv.z, vv.w };
        float rv[4] = { 0.f, 0.f, 0.f, 0.f };
        if (resid) {
            float4 rr = *(const float4*)(resid + (size_t)node * D + d0);
            rv[0] = rr.x; rv[1] = rr.y; rv[2] = rr.z; rv[3] = rr.w;
        }
#pragma unroll
        for (int q = 0; q < 4; q++) {
            float val = (o[q] - mvx[q]) * rsqrtf(vvx[q] + 1e-5f) * gvx[q] + bvx[q] + rv[q];
            o[q] = (val > 0.f) ? val : expm1f(val);
        }
    }

    if (!FINAL) {
        *(float4*)(out + (size_t)node * D + d0) = make_float4(o[0], o[1], o[2], o[3]);
    } else {
        float4 x4 = *(const float4*)(xi + (size_t)node * 128 + 4 * l);
        float v[4] = { o[0] + x4.x, o[1] + x4.y, o[2] + x4.z, o[3] + x4.w };
        int d = 4 * l;
        float z0 = 0.f, z1 = 0.f;
#pragma unroll
        for (int q = 0; q < 4; q++) {
            z0 = fmaf(v[q], fcW[(d + q) * 2], z0);
            z1 = fmaf(v[q], fcW[(d + q) * 2 + 1], z1);
        }
#pragma unroll
        for (int off = 16; off; off >>= 1) {
            z0 += __shfl_down_sync(0xffffffffu, z0, off);
            z1 += __shfl_down_sync(0xffffffffu, z1, off);
        }
        if (l == 0) {
            z0 += fcb[0]; z1 += fcb[1];
            float mx = fmaxf(z0, z1);
            float lse = mx + logf(expf(z0 - mx) + expf(z1 - mx));
            fout[node * 2] = z0 - lse;
            fout[node * 2 + 1] = z1 - lse;
        }
    }
}

// ---------------- launch ----------------
extern "C" void kernel_launch(void* const* d_in, const int* in_sizes, int n_in,
                              void* d_out, int out_size) {
    const float* x   = (const float*)d_in[0];
    const int*   ei  = (const int*)d_in[1];
    const float* W1  = (const float*)d_in[2];
    const float* a1s = (const float*)d_in[3];
    const float* a1d = (const float*)d_in[4];
    const float* b1  = (const float*)d_in[5];
    const float* g1  = (const float*)d_in[6];
    const float* be1 = (const float*)d_in[7];
    const float* m1  = (const float*)d_in[8];
    const float* v1  = (const float*)d_in[9];
    const float* W2  = (const float*)d_in[10];
    const float* a2s = (const float*)d_in[11];
    const float* a2d = (const float*)d_in[12];
    const float* b2  = (const float*)d_in[13];
    const float* g2  = (const float*)d_in[14];
    const float* be2 = (const float*)d_in[15];
    const float* m2  = (const float*)d_in[16];
    const float* v2  = (const float*)d_in[17];
    const float* W3  = (const float*)d_in[18];
    const float* a3s = (const float*)d_in[19];
    const float* a3d = (const float*)d_in[20];
    const float* b3  = (const float*)d_in[21];
    const float* fcW = (const float*)d_in[22];
    const float* fcb = (const float*)d_in[23];
    const float* skW = (const float*)d_in[24];
    const float* skb = (const float*)d_in[25];
    const float* temp = (const float*)d_in[26];

    int n = in_sizes[0] / FIN;   // 50000
    int e = in_sizes[1] / 2;     // 800000
    const int* src = ei;
    const int* dst = ei + e;

    float *buf1, *buf2, *buf3, *xinit, *asrc, *adst;
    cudaGetSymbolAddress((void**)&buf1, g_buf1);
    cudaGetSymbolAddress((void**)&buf2, g_buf2);
    cudaGetSymbolAddress((void**)&buf3, g_buf3);
    cudaGetSymbolAddress((void**)&xinit, g_xinit);
    cudaGetSymbolAddress((void**)&asrc, g_asrc);
    cudaGetSymbolAddress((void**)&adst, g_adst);

    int nb256 = (n + 255) / 256;
    int eb256 = (e + 255) / 256;
    int wg1 = (n * 32 + 255) / 256;
    int wg2 = (n * 64 + 255) / 256;
    int gm = (n + 127) / 128;

    // CSR build (by destination)
    k_zero<<<nb256, 256>>>(n);
    k_count<<<eb256, 256>>>(dst, e);
    k_scan<<<1, 1024>>>(n);
    k_scatter<<<eb256, 256>>>(src, dst, e);

    // skip connection: x_init = x @ skW + skb
    k_sgemm<false><<<dim3(1, gm), 256>>>(x, skW, xinit, n, 128, FIN, skb, nullptr,
                                         nullptr, nullptr, nullptr, nullptr, 4);

    // ---- layer 1 (no self loops) ----
    k_sgemm<true><<<dim3(2, gm), 256>>>(x, W1, buf1, n, 256, FIN, nullptr, nullptr,
                                        asrc, adst, a1s, a1d, 8);
    k_agg<8, false, true, false><<<wg2, 256>>>(buf1, b1, buf2, n, g1, be1, m1, v1, nullptr,
                                               nullptr, nullptr, nullptr, nullptr);

    // ---- layer 2 (self loops, residual) ----
    k_sgemm<true><<<dim3(2, gm), 256>>>(buf2, W2, buf1, n, 256, 256, nullptr, nullptr,
                                        asrc, adst, a2s, a2d, 8);
    k_agg<8, true, true, false><<<wg2, 256>>>(buf1, b2, buf3, n, g2, be2, m2, v2, buf2,
                                              nullptr, nullptr, nullptr, nullptr);

    // ---- layer 3 (self loops, temp folded into GEMM scale), fused final ----
    k_sgemm<true><<<dim3(1, gm), 256>>>(buf3, W3, buf1, n, 128, 256, nullptr, temp,
                                        asrc, adst, a3s, a3d, 4);
    k_agg<4, true, false, true><<<wg1, 256>>>(buf1, b3, nullptr, n, nullptr, nullptr, nullptr,
                                              nullptr, nullptr, xinit, fcW, fcb, (float*)d_out);
}

// round 6
// speedup vs baseline: 1.7182x; 1.2808x over previous
#include <cuda_runtime.h>
#include <cuda_bf16.h>
#include <math.h>
#include <cstdint>

#define NN 50000
#define EE 800000
#define FIN 165

// ---------------- scratch (device globals; no allocation allowed) ----------------
__device__ float g_buf1[NN * 256];
__device__ float g_buf2[NN * 256];
__device__ float g_buf3[NN * 256];
__device__ float g_xinit[NN * 128];
__device__ float g_asrc[NN * 8];
__device__ float g_adst[NN * 8];
__device__ int   g_rowptr[NN + 1];
__device__ int   g_cursor[NN];
__device__ int   g_col[EE];

// ---------------- CSR build (by destination) ----------------
__global__ void k_zero(int n) {
    int i = blockIdx.x * blockDim.x + threadIdx.x;
    if (i < n) g_cursor[i] = 0;
}
__global__ void k_count(const int* __restrict__ dst, int e) {
    int i = blockIdx.x * blockDim.x + threadIdx.x;
    if (i < e) atomicAdd(&g_cursor[dst[i]], 1);
}
__global__ void k_scan(int n) {
    __shared__ int sh[1024];
    int t = threadIdx.x;
    int C = (n + 1023) / 1024;
    int base = t * C;
    int local = 0;
    for (int j = 0; j < C; j++) { int i = base + j; if (i < n) local += g_cursor[i]; }
    sh[t] = local;
    __syncthreads();
    for (int off = 1; off < 1024; off <<= 1) {
        int v = (t >= off) ? sh[t - off] : 0;
        __syncthreads();
        sh[t] += v;
        __syncthreads();
    }
    int run = sh[t] - local;
    for (int j = 0; j < C; j++) {
        int i = base + j;
        if (i < n) { int d = g_cursor[i]; g_rowptr[i] = run; g_cursor[i] = run; run += d; }
    }
    if (t == 1023) g_rowptr[n] = sh[1023];
}
__global__ void k_scatter(const int* __restrict__ src, const int* __restrict__ dst, int e) {
    int i = blockIdx.x * blockDim.x + threadIdx.x;
    if (i >= e) return;
    int pos = atomicAdd(&g_cursor[dst[i]], 1);
    g_col[pos] = src[i];
}

// ---------------- bf16 split + mma helper ----------------
__device__ __forceinline__ void split_bf16(float v, __nv_bfloat16& h, __nv_bfloat16& l) {
    h = __float2bfloat16_rn(v);
    l = __float2bfloat16_rn(v - __bfloat162float(h));
}

__device__ __forceinline__ void mma16816(float* c, const uint32_t* a, const uint32_t* b) {
    asm volatile(
        "mma.sync.aligned.m16n8k16.row.col.f32.bf16.bf16.f32 "
        "{%0,%1,%2,%3}, {%4,%5,%6,%7}, {%8,%9}, {%0,%1,%2,%3};"
        : "+f"(c[0]), "+f"(c[1]), "+f"(c[2]), "+f"(c[3])
        : "r"(a[0]), "r"(a[1]), "r"(a[2]), "r"(a[3]), "r"(b[0]), "r"(b[1]));
}

// ================= bf16x3 tensor-core GEMM, 128x128 block, BK=16, double-buffered =========
// C[M,N] = A[M,K] @ B[K,N] (*scale) (+bias); optional fused per-head attention dot products.
// 8 warps: warp_m = wid&3 (32 rows), warp_n = wid>>2 (64 cols). Requires N % 128 == 0.
#define LDS_STRIDE 18   // bf16 elements per smem row (36B) — bank-friendly

template <bool ATTN>
__global__ void __launch_bounds__(256, 1)
k_mgemm(const float* __restrict__ A, const float* __restrict__ B, float* __restrict__ C,
        int M, int N, int K,
        const float* __restrict__ bias, const float* __restrict__ scale,
        float* __restrict__ asrc, float* __restrict__ adst,
        const float* __restrict__ a_s, const float* __restrict__ a_d, int H) {
    __shared__ __align__(16) __nv_bfloat16 AsH[2][128][LDS_STRIDE];
    __shared__ __align__(16) __nv_bfloat16 AsL[2][128][LDS_STRIDE];
    __shared__ __align__(16) __nv_bfloat16 BsH[2][128][LDS_STRIDE];
    __shared__ __align__(16) __nv_bfloat16 BsL[2][128][LDS_STRIDE];

    int tid = threadIdx.x;
    int wid = tid >> 5;
    int lane = tid & 31;
    int g = lane >> 2, tg = lane & 3;
    int warp_m = wid & 3;          // 4 warps along M, 32 rows each
    int warp_n = wid >> 2;         // 2 warps along N, 64 cols each
    int bm = blockIdx.y * 128;
    int bn = blockIdx.x * 128;

    float acc[2][8][4];
#pragma unroll
    for (int mt = 0; mt < 2; mt++)
#pragma unroll
        for (int nt = 0; nt < 8; nt++)
#pragma unroll
            for (int q = 0; q < 4; q++) acc[mt][nt][q] = 0.f;

    float av[8], bv[8];
    int nk = (K + 15) >> 4;

    // ---- prologue: load + store tile 0 ----
    {
#pragma unroll
        for (int i = 0; i < 8; i++) {
            int idx = tid + i * 256;
            int r = idx >> 4, kk = idx & 15;
            int gr = bm + r;
            av[i] = (gr < M && kk < K) ? A[(size_t)gr * K + kk] : 0.f;
        }
#pragma unroll
        for (int i = 0; i < 8; i++) {
            int idx = tid + i * 256;
            int k = idx >> 7, nn = idx & 127;
            bv[i] = (k < K) ? B[(size_t)k * N + bn + nn] : 0.f;
        }
#pragma unroll
        for (int i = 0; i < 8; i++) {
            int idx = tid + i * 256;
            int r = idx >> 4, kk = idx & 15;
            __nv_bfloat16 h, l; split_bf16(av[i], h, l);
            AsH[0][r][kk] = h; AsL[0][r][kk] = l;
        }
#pragma unroll
        for (int i = 0; i < 8; i++) {
            int idx = tid + i * 256;
            int k = idx >> 7, nn = idx & 127;
            __nv_bfloat16 h, l; split_bf16(bv[i], h, l);
            BsH[0][nn][k] = h; BsL[0][nn][k] = l;
        }
    }
    __syncthreads();

    for (int t = 0; t < nk; t++) {
        int cur = t & 1;
        if (t + 1 < nk) {
            int k0 = (t + 1) << 4;
#pragma unroll
            for (int i = 0; i < 8; i++) {
                int idx = tid + i * 256;
                int r = idx >> 4, kk = idx & 15;
                int gr = bm + r, gk = k0 + kk;
                av[i] = (gr < M && gk < K) ? A[(size_t)gr * K + gk] : 0.f;
            }
#pragma unroll
            for (int i = 0; i < 8; i++) {
                int idx = tid + i * 256;
                int k = idx >> 7, nn = idx & 127;
                int gk = k0 + k;
                bv[i] = (gk < K) ? B[(size_t)gk * N + bn + nn] : 0.f;
            }
        }

        // ---- compute on buffer cur ----
        {
            uint32_t aH[2][4], aL[2][4];
#pragma unroll
            for (int mt = 0; mt < 2; mt++) {
                int r0 = warp_m * 32 + mt * 16;
                aH[mt][0] = *(const uint32_t*)&AsH[cur][r0 + g][tg * 2];
                aH[mt][1] = *(const uint32_t*)&AsH[cur][r0 + g + 8][tg * 2];
                aH[mt][2] = *(const uint32_t*)&AsH[cur][r0 + g][tg * 2 + 8];
                aH[mt][3] = *(const uint32_t*)&AsH[cur][r0 + g + 8][tg * 2 + 8];
                aL[mt][0] = *(const uint32_t*)&AsL[cur][r0 + g][tg * 2];
                aL[mt][1] = *(const uint32_t*)&AsL[cur][r0 + g + 8][tg * 2];
                aL[mt][2] = *(const uint32_t*)&AsL[cur][r0 + g][tg * 2 + 8];
                aL[mt][3] = *(const uint32_t*)&AsL[cur][r0 + g + 8][tg * 2 + 8];
            }
#pragma unroll
            for (int nt = 0; nt < 8; nt++) {
                int n0 = warp_n * 64 + nt * 8 + g;
                uint32_t bH[2], bL[2];
                bH[0] = *(const uint32_t*)&BsH[cur][n0][tg * 2];
                bH[1] = *(const uint32_t*)&BsH[cur][n0][tg * 2 + 8];
                bL[0] = *(const uint32_t*)&BsL[cur][n0][tg * 2];
                bL[1] = *(const uint32_t*)&BsL[cur][n0][tg * 2 + 8];
#pragma unroll
                for (int mt = 0; mt < 2; mt++) {
                    mma16816(acc[mt][nt], aH[mt], bH);
                    mma16816(acc[mt][nt], aH[mt], bL);
                    mma16816(acc[mt][nt], aL[mt], bH);
                }
            }
        }

        if (t + 1 < nk) {
            __syncthreads();
            int nxt = cur ^ 1;
#pragma unroll
            for (int i = 0; i < 8; i++) {
                int idx = tid + i * 256;
                int r = idx >> 4, kk = idx & 15;
                __nv_bfloat16 h, l; split_bf16(av[i], h, l);
                AsH[nxt][r][kk] = h; AsL[nxt][r][kk] = l;
            }
#pragma unroll
            for (int i = 0; i < 8; i++) {
                int idx = tid + i * 256;
                int k = idx >> 7, nn = idx & 127;
                __nv_bfloat16 h, l; split_bf16(bv[i], h, l);
                BsH[nxt][nn][k] = h; BsL[nxt][nn][k] = l;
            }
            __syncthreads();
        }
    }

    // ---- epilogue ----
    float scl = scale ? *scale : 1.0f;
    int cbase = bn + warp_n * 64;
#pragma unroll
    for (int mt = 0; mt < 2; mt++) {
#pragma unroll
        for (int rh = 0; rh < 2; rh++) {
            int r = bm + warp_m * 32 + mt * 16 + rh * 8 + g;
            float v[8][2];
            float ds0 = 0.f, dd0 = 0.f, ds1 = 0.f, dd1 = 0.f;
#pragma unroll
            for (int nt = 0; nt < 8; nt++) {
                int c = cbase + nt * 8 + tg * 2;
                float v0 = acc[mt][nt][rh * 2 + 0] * scl;
                float v1 = acc[mt][nt][rh * 2 + 1] * scl;
                if (bias) { v0 += bias[c]; v1 += bias[c + 1]; }
                v[nt][0] = v0; v[nt][1] = v1;
                if (ATTN) {
                    float s0 = a_s[c], s1 = a_s[c + 1];
                    float d0 = a_d[c], d1 = a_d[c + 1];
                    if (nt < 4) {
                        ds0 = fmaf(v0, s0, fmaf(v1, s1, ds0));
                        dd0 = fmaf(v0, d0, fmaf(v1, d1, dd0));
                    } else {
                        ds1 = fmaf(v0, s0, fmaf(v1, s1, ds1));
                        dd1 = fmaf(v0, d0, fmaf(v1, d1, dd1));
                    }
                }
            }
            if (ATTN) {
                ds0 += __shfl_xor_sync(0xffffffffu, ds0, 1);
                ds0 += __shfl_xor_sync(0xffffffffu, ds0, 2);
                dd0 += __shfl_xor_sync(0xffffffffu, dd0, 1);
                dd0 += __shfl_xor_sync(0xffffffffu, dd0, 2);
                ds1 += __shfl_xor_sync(0xffffffffu, ds1, 1);
                ds1 += __shfl_xor_sync(0xffffffffu, ds1, 2);
                dd1 += __shfl_xor_sync(0xffffffffu, dd1, 1);
                dd1 += __shfl_xor_sync(0xffffffffu, dd1, 2);
            }
            if (r < M) {
#pragma unroll
                for (int nt = 0; nt < 8; nt++) {
                    int c = cbase + nt * 8 + tg * 2;
                    *(float2*)(C + (size_t)r * N + c) = make_float2(v[nt][0], v[nt][1]);
                }
                if (ATTN && tg == 0) {
                    int h0 = cbase >> 5;
                    asrc[(size_t)r * H + h0]     = ds0;
                    asrc[(size_t)r * H + h0 + 1] = ds1;
                    adst[(size_t)r * H + h0]     = dd0;
                    adst[(size_t)r * H + h0 + 1] = dd1;
                }
            }
        }
    }
}

// ---------------- GAT aggregation: single pass, warp per (node, half), 2x unrolled ----------
template <int H, bool SL, bool BN, bool FINAL>
__global__ void k_agg(const float* __restrict__ h, const float* __restrict__ bias,
                      float* __restrict__ out, int n,
                      const float* __restrict__ bg, const float* __restrict__ bb,
                      const float* __restrict__ bmean, const float* __restrict__ bvar,
                      const float* __restrict__ resid,
                      const float* __restrict__ xi, const float* __restrict__ fcW,
                      const float* __restrict__ fcb, float* __restrict__ fout) {
    const int D = H * 32;
    constexpr int SHIFT = (H == 8) ? 1 : 0;
    int gw = (blockIdx.x * blockDim.x + threadIdx.x) >> 5;
    int l = threadIdx.x & 31;
    int node = gw >> SHIFT;
    int half = (H == 8) ? (gw & 1) : 0;
    if (node >= n) return;

    int myhead = half * 4 + (l >> 3);
    int d0 = half * 128 + 4 * l;
    float ad = g_adst[node * H + myhead];
    int rs = g_rowptr[node], re = g_rowptr[node + 1];

    float den = 0.f;
    float4 acc = make_float4(0.f, 0.f, 0.f, 0.f);
    if (SL) {
        float t = g_asrc[node * H + myhead] + ad;
        t = (t > 0.f) ? t : 0.2f * t;
        float ex = __expf(t);
        den += ex;
        float4 v = *(const float4*)(h + (size_t)node * D + d0);
        acc.x += ex * v.x; acc.y += ex * v.y; acc.z += ex * v.z; acc.w += ex * v.w;
    }
    int j = rs;
    for (; j + 1 < re; j += 2) {
        int s0 = g_col[j];
        int s1 = g_col[j + 1];
        float t0 = g_asrc[s0 * H + myhead] + ad;
        float t1 = g_asrc[s1 * H + myhead] + ad;
        t0 = (t0 > 0.f) ? t0 : 0.2f * t0;
        t1 = (t1 > 0.f) ? t1 : 0.2f * t1;
        float e0 = __expf(t0);
        float e1 = __expf(t1);
        float4 v0 = *(const float4*)(h + (size_t)s0 * D + d0);
        float4 v1 = *(const float4*)(h + (size_t)s1 * D + d0);
        den += e0 + e1;
        acc.x += e0 * v0.x + e1 * v1.x;
        acc.y += e0 * v0.y + e1 * v1.y;
        acc.z += e0 * v0.z + e1 * v1.z;
        acc.w += e0 * v0.w + e1 * v1.w;
    }
    if (j < re) {
        int s = g_col[j];
        float t = g_asrc[s * H + myhead] + ad;
        t = (t > 0.f) ? t : 0.2f * t;
        float ex = __expf(t);
        den += ex;
        float4 v = *(const float4*)(h + (size_t)s * D + d0);
        acc.x += ex * v.x; acc.y += ex * v.y; acc.z += ex * v.z; acc.w += ex * v.w;
    }

    float inv = 1.f / (den + 1e-16f);
    float4 b4 = *(const float4*)(bias + d0);
    float o[4] = { acc.x * inv + b4.x, acc.y * inv + b4.y, acc.z * inv + b4.z, acc.w * inv + b4.w };

    if (BN) {
        float4 gg = *(const float4*)(bg + d0);
        float4 bbv = *(const float4*)(bb + d0);
        float4 mm = *(const float4*)(bmean + d0);
        float4 vv = *(const float4*)(bvar + d0);
        float gvx[4] = { gg.x, gg.y, gg.z, gg.w }, bvx[4] = { bbv.x, bbv.y, bbv.z, bbv.w };
        float mvx[4] = { mm.x, mm.y, mm.z, mm.w }, vvx[4] = { vv.x, vv.y, vv.z, vv.w };
        float rv[4] = { 0.f, 0.f, 0.f, 0.f };
        if (resid) {
            float4 rr = *(const float4*)(resid + (size_t)node * D + d0);
            rv[0] = rr.x; rv[1] = rr.y; rv[2] = rr.z; rv[3] = rr.w;
        }
#pragma unroll
        for (int q = 0; q < 4; q++) {
            float val = (o[q] - mvx[q]) * rsqrtf(vvx[q] + 1e-5f) * gvx[q] + bvx[q] + rv[q];
            o[q] = (val > 0.f) ? val : expm1f(val);
        }
    }

    if (!FINAL) {
        *(float4*)(out + (size_t)node * D + d0) = make_float4(o[0], o[1], o[2], o[3]);
    } else {
        float4 x4 = *(const float4*)(xi + (size_t)node * 128 + 4 * l);
        float v[4] = { o[0] + x4.x, o[1] + x4.y, o[2] + x4.z, o[3] + x4.w };
        int d = 4 * l;
        float z0 = 0.f, z1 = 0.f;
#pragma unroll
        for (int q = 0; q < 4; q++) {
            z0 = fmaf(v[q], fcW[(d + q) * 2], z0);
            z1 = fmaf(v[q], fcW[(d + q) * 2 + 1], z1);
        }
#pragma unroll
        for (int off = 16; off; off >>= 1) {
            z0 += __shfl_down_sync(0xffffffffu, z0, off);
            z1 += __shfl_down_sync(0xffffffffu, z1, off);
        }
        if (l == 0) {
            z0 += fcb[0]; z1 += fcb[1];
            float mx = fmaxf(z0, z1);
            float lse = mx + logf(expf(z0 - mx) + expf(z1 - mx));
            fout[node * 2] = z0 - lse;
            fout[node * 2 + 1] = z1 - lse;
        }
    }
}

// ---------------- launch ----------------
extern "C" void kernel_launch(void* const* d_in, const int* in_sizes, int n_in,
                              void* d_out, int out_size) {
    const float* x   = (const float*)d_in[0];
    const int*   ei  = (const int*)d_in[1];
    const float* W1  = (const float*)d_in[2];
    const float* a1s = (const float*)d_in[3];
    const float* a1d = (const float*)d_in[4];
    const float* b1  = (const float*)d_in[5];
    const float* g1  = (const float*)d_in[6];
    const float* be1 = (const float*)d_in[7];
    const float* m1  = (const float*)d_in[8];
    const float* v1  = (const float*)d_in[9];
    const float* W2  = (const float*)d_in[10];
    const float* a2s = (const float*)d_in[11];
    const float* a2d = (const float*)d_in[12];
    const float* b2  = (const float*)d_in[13];
    const float* g2  = (const float*)d_in[14];
    const float* be2 = (const float*)d_in[15];
    const float* m2  = (const float*)d_in[16];
    const float* v2  = (const float*)d_in[17];
    const float* W3  = (const float*)d_in[18];
    const float* a3s = (const float*)d_in[19];
    const float* a3d = (const float*)d_in[20];
    const float* b3  = (const float*)d_in[21];
    const float* fcW = (const float*)d_in[22];
    const float* fcb = (const float*)d_in[23];
    const float* skW = (const float*)d_in[24];
    const float* skb = (const float*)d_in[25];
    const float* temp = (const float*)d_in[26];

    int n = in_sizes[0] / FIN;   // 50000
    int e = in_sizes[1] / 2;     // 800000
    const int* src = ei;
    const int* dst = ei + e;

    float *buf1, *buf2, *buf3, *xinit, *asrc, *adst;
    cudaGetSymbolAddress((void**)&buf1, g_buf1);
    cudaGetSymbolAddress((void**)&buf2, g_buf2);
    cudaGetSymbolAddress((void**)&buf3, g_buf3);
    cudaGetSymbolAddress((void**)&xinit, g_xinit);
    cudaGetSymbolAddress((void**)&asrc, g_asrc);
    cudaGetSymbolAddress((void**)&adst, g_adst);

    int nb256 = (n + 255) / 256;
    int eb256 = (e + 255) / 256;
    int wg1 = (n * 32 + 255) / 256;
    int wg2 = (n * 64 + 255) / 256;
    int gm = (n + 127) / 128;

    // CSR build (by destination)
    k_zero<<<nb256, 256>>>(n);
    k_count<<<eb256, 256>>>(dst, e);
    k_scan<<<1, 1024>>>(n);
    k_scatter<<<eb256, 256>>>(src, dst, e);

    // skip connection: x_init = x @ skW + skb
    k_mgemm<false><<<dim3(1, gm), 256>>>(x, skW, xinit, n, 128, FIN, skb, nullptr,
                                         nullptr, nullptr, nullptr, nullptr, 4);

    // ---- layer 1 (no self loops) ----
    k_mgemm<true><<<dim3(2, gm), 256>>>(x, W1, buf1, n, 256, FIN, nullptr, nullptr,
                                        asrc, adst, a1s, a1d, 8);
    k_agg<8, false, true, false><<<wg2, 256>>>(buf1, b1, buf2, n, g1, be1, m1, v1, nullptr,
                                               nullptr, nullptr, nullptr, nullptr);

    // ---- layer 2 (self loops, residual) ----
    k_mgemm<true><<<dim3(2, gm), 256>>>(buf2, W2, buf1, n, 256, 256, nullptr, nullptr,
                                        asrc, adst, a2s, a2d, 8);
    k_agg<8, true, true, false><<<wg2, 256>>>(buf1, b2, buf3, n, g2, be2, m2, v2, buf2,
                                              nullptr, nullptr, nullptr, nullptr);

    // ---- layer 3 (self loops, temp folded into GEMM scale), fused final ----
    k_mgemm<true><<<dim3(1, gm), 256>>>(buf3, W3, buf1, n, 128, 256, nullptr, temp,
                                        asrc, adst, a3s, a3d, 4);
    k_agg<4, true, false, true><<<wg1, 256>>>(buf1, b3, nullptr, n, nullptr, nullptr, nullptr,
                                              nullptr, nullptr, xinit, fcW, fcb, (float*)d_out);
}

// round 7
// speedup vs baseline: 1.7785x; 1.0351x over previous
#include <cuda_runtime.h>
#include <cuda_fp16.h>
#include <cuda_bf16.h>
#include <math.h>
#include <cstdint>

#define NN 50000
#define EE 800000
#define FIN 165

// ---------------- scratch (device globals; no allocation allowed) ----------------
__device__ uint32_t g_hh[NN * 128];     // packed half2 features (256 halves/row max)
__device__ float g_buf2[NN * 256];
__device__ float g_buf3[NN * 256];
__device__ float g_xinit[NN * 128];
__device__ float g_asrc[NN * 8];
__device__ float g_adst[NN * 8];
__device__ int   g_rowptr[NN + 1];
__device__ int   g_cursor[NN];
__device__ int   g_col[EE];

// ---------------- CSR build (by destination) ----------------
__global__ void k_zero(int n) {
    int i = blockIdx.x * blockDim.x + threadIdx.x;
    if (i < n) g_cursor[i] = 0;
}
__global__ void k_count(const int* __restrict__ dst, int e) {
    int i = blockIdx.x * blockDim.x + threadIdx.x;
    if (i < e) atomicAdd(&g_cursor[dst[i]], 1);
}
__global__ void k_scan(int n) {
    __shared__ int sh[1024];
    int t = threadIdx.x;
    int C = (n + 1023) / 1024;
    int base = t * C;
    int local = 0;
    for (int j = 0; j < C; j++) { int i = base + j; if (i < n) local += g_cursor[i]; }
    sh[t] = local;
    __syncthreads();
    for (int off = 1; off < 1024; off <<= 1) {
        int v = (t >= off) ? sh[t - off] : 0;
        __syncthreads();
        sh[t] += v;
        __syncthreads();
    }
    int run = sh[t] - local;
    for (int j = 0; j < C; j++) {
        int i = base + j;
        if (i < n) { int d = g_cursor[i]; g_rowptr[i] = run; g_cursor[i] = run; run += d; }
    }
    if (t == 1023) g_rowptr[n] = sh[1023];
}
__global__ void k_scatter(const int* __restrict__ src, const int* __restrict__ dst, int e) {
    int i = blockIdx.x * blockDim.x + threadIdx.x;
    if (i >= e) return;
    int pos = atomicAdd(&g_cursor[dst[i]], 1);
    g_col[pos] = src[i];
}

// ---------------- bf16 split + mma helper ----------------
__device__ __forceinline__ void split_bf16(float v, __nv_bfloat16& h, __nv_bfloat16& l) {
    h = __float2bfloat16_rn(v);
    l = __float2bfloat16_rn(v - __bfloat162float(h));
}

__device__ __forceinline__ void mma16816(float* c, const uint32_t* a, const uint32_t* b) {
    asm volatile(
        "mma.sync.aligned.m16n8k16.row.col.f32.bf16.bf16.f32 "
        "{%0,%1,%2,%3}, {%4,%5,%6,%7}, {%8,%9}, {%0,%1,%2,%3};"
        : "+f"(c[0]), "+f"(c[1]), "+f"(c[2]), "+f"(c[3])
        : "r"(a[0]), "r"(a[1]), "r"(a[2]), "r"(a[3]), "r"(b[0]), "r"(b[1]));
}

// ================= bf16x3 tensor-core GEMM, 128x128 block, BK=16, double-buffered =========
// ATTN=true : writes packed-half2 features to hh + fused per-head attention dots (no fp32 C).
// ATTN=false: writes fp32 C (+bias).
#define LDS_STRIDE 18

template <bool ATTN>
__global__ void __launch_bounds__(256, 1)
k_mgemm(const float* __restrict__ A, const float* __restrict__ B, float* __restrict__ C,
        uint32_t* __restrict__ hh, int M, int N, int K,
        const float* __restrict__ bias, const float* __restrict__ scale,
        float* __restrict__ asrc, float* __restrict__ adst,
        const float* __restrict__ a_s, const float* __restrict__ a_d, int H) {
    __shared__ __align__(16) __nv_bfloat16 AsH[2][128][LDS_STRIDE];
    __shared__ __align__(16) __nv_bfloat16 AsL[2][128][LDS_STRIDE];
    __shared__ __align__(16) __nv_bfloat16 BsH[2][128][LDS_STRIDE];
    __shared__ __align__(16) __nv_bfloat16 BsL[2][128][LDS_STRIDE];

    int tid = threadIdx.x;
    int wid = tid >> 5;
    int lane = tid & 31;
    int g = lane >> 2, tg = lane & 3;
    int warp_m = wid & 3;
    int warp_n = wid >> 2;
    int bm = blockIdx.y * 128;
    int bn = blockIdx.x * 128;

    float acc[2][8][4];
#pragma unroll
    for (int mt = 0; mt < 2; mt++)
#pragma unroll
        for (int nt = 0; nt < 8; nt++)
#pragma unroll
            for (int q = 0; q < 4; q++) acc[mt][nt][q] = 0.f;

    float av[8], bv[8];
    int nk = (K + 15) >> 4;

    {
#pragma unroll
        for (int i = 0; i < 8; i++) {
            int idx = tid + i * 256;
            int r = idx >> 4, kk = idx & 15;
            int gr = bm + r;
            av[i] = (gr < M && kk < K) ? A[(size_t)gr * K + kk] : 0.f;
        }
#pragma unroll
        for (int i = 0; i < 8; i++) {
            int idx = tid + i * 256;
            int k = idx >> 7, nn = idx & 127;
            bv[i] = (k < K) ? B[(size_t)k * N + bn + nn] : 0.f;
        }
#pragma unroll
        for (int i = 0; i < 8; i++) {
            int idx = tid + i * 256;
            int r = idx >> 4, kk = idx & 15;
            __nv_bfloat16 h, l; split_bf16(av[i], h, l);
            AsH[0][r][kk] = h; AsL[0][r][kk] = l;
        }
#pragma unroll
        for (int i = 0; i < 8; i++) {
            int idx = tid + i * 256;
            int k = idx >> 7, nn = idx & 127;
            __nv_bfloat16 h, l; split_bf16(bv[i], h, l);
            BsH[0][nn][k] = h; BsL[0][nn][k] = l;
        }
    }
    __syncthreads();

    for (int t = 0; t < nk; t++) {
        int cur = t & 1;
        if (t + 1 < nk) {
            int k0 = (t + 1) << 4;
#pragma unroll
            for (int i = 0; i < 8; i++) {
                int idx = tid + i * 256;
                int r = idx >> 4, kk = idx & 15;
                int gr = bm + r, gk = k0 + kk;
                av[i] = (gr < M && gk < K) ? A[(size_t)gr * K + gk] : 0.f;
            }
#pragma unroll
            for (int i = 0; i < 8; i++) {
                int idx = tid + i * 256;
                int k = idx >> 7, nn = idx & 127;
                int gk = k0 + k;
                bv[i] = (gk < K) ? B[(size_t)gk * N + bn + nn] : 0.f;
            }
        }
        {
            uint32_t aH[2][4], aL[2][4];
#pragma unroll
            for (int mt = 0; mt < 2; mt++) {
                int r0 = warp_m * 32 + mt * 16;
                aH[mt][0] = *(const uint32_t*)&AsH[cur][r0 + g][tg * 2];
                aH[mt][1] = *(const uint32_t*)&AsH[cur][r0 + g + 8][tg * 2];
                aH[mt][2] = *(const uint32_t*)&AsH[cur][r0 + g][tg * 2 + 8];
                aH[mt][3] = *(const uint32_t*)&AsH[cur][r0 + g + 8][tg * 2 + 8];
                aL[mt][0] = *(const uint32_t*)&AsL[cur][r0 + g][tg * 2];
                aL[mt][1] = *(const uint32_t*)&AsL[cur][r0 + g + 8][tg * 2];
                aL[mt][2] = *(const uint32_t*)&AsL[cur][r0 + g][tg * 2 + 8];
                aL[mt][3] = *(const uint32_t*)&AsL[cur][r0 + g + 8][tg * 2 + 8];
            }
#pragma unroll
            for (int nt = 0; nt < 8; nt++) {
                int n0 = warp_n * 64 + nt * 8 + g;
                uint32_t bH[2], bL[2];
                bH[0] = *(const uint32_t*)&BsH[cur][n0][tg * 2];
                bH[1] = *(const uint32_t*)&BsH[cur][n0][tg * 2 + 8];
                bL[0] = *(const uint32_t*)&BsL[cur][n0][tg * 2];
                bL[1] = *(const uint32_t*)&BsL[cur][n0][tg * 2 + 8];
#pragma unroll
                for (int mt = 0; mt < 2; mt++) {
                    mma16816(acc[mt][nt], aH[mt], bH);
                    mma16816(acc[mt][nt], aH[mt], bL);
                    mma16816(acc[mt][nt], aL[mt], bH);
                }
            }
        }
        if (t + 1 < nk) {
            __syncthreads();
            int nxt = cur ^ 1;
#pragma unroll
            for (int i = 0; i < 8; i++) {
                int idx = tid + i * 256;
                int r = idx >> 4, kk = idx & 15;
                __nv_bfloat16 h, l; split_bf16(av[i], h, l);
                AsH[nxt][r][kk] = h; AsL[nxt][r][kk] = l;
            }
#pragma unroll
            for (int i = 0; i < 8; i++) {
                int idx = tid + i * 256;
                int k = idx >> 7, nn = idx & 127;
                __nv_bfloat16 h, l; split_bf16(bv[i], h, l);
                BsH[nxt][nn][k] = h; BsL[nxt][nn][k] = l;
            }
            __syncthreads();
        }
    }

    // ---- epilogue ----
    float scl = scale ? *scale : 1.0f;
    int cbase = bn + warp_n * 64;
    int halfN = N >> 1;
#pragma unroll
    for (int mt = 0; mt < 2; mt++) {
#pragma unroll
        for (int rh = 0; rh < 2; rh++) {
            int r = bm + warp_m * 32 + mt * 16 + rh * 8 + g;
            float v[8][2];
            float ds0 = 0.f, dd0 = 0.f, ds1 = 0.f, dd1 = 0.f;
#pragma unroll
            for (int nt = 0; nt < 8; nt++) {
                int c = cbase + nt * 8 + tg * 2;
                float v0 = acc[mt][nt][rh * 2 + 0] * scl;
                float v1 = acc[mt][nt][rh * 2 + 1] * scl;
                if (bias) { v0 += bias[c]; v1 += bias[c + 1]; }
                v[nt][0] = v0; v[nt][1] = v1;
                if (ATTN) {
                    float s0 = a_s[c], s1 = a_s[c + 1];
                    float d0 = a_d[c], d1 = a_d[c + 1];
                    if (nt < 4) {
                        ds0 = fmaf(v0, s0, fmaf(v1, s1, ds0));
                        dd0 = fmaf(v0, d0, fmaf(v1, d1, dd0));
                    } else {
                        ds1 = fmaf(v0, s0, fmaf(v1, s1, ds1));
                        dd1 = fmaf(v0, d0, fmaf(v1, d1, dd1));
                    }
                }
            }
            if (ATTN) {
                ds0 += __shfl_xor_sync(0xffffffffu, ds0, 1);
                ds0 += __shfl_xor_sync(0xffffffffu, ds0, 2);
                dd0 += __shfl_xor_sync(0xffffffffu, dd0, 1);
                dd0 += __shfl_xor_sync(0xffffffffu, dd0, 2);
                ds1 += __shfl_xor_sync(0xffffffffu, ds1, 1);
                ds1 += __shfl_xor_sync(0xffffffffu, ds1, 2);
                dd1 += __shfl_xor_sync(0xffffffffu, dd1, 1);
                dd1 += __shfl_xor_sync(0xffffffffu, dd1, 2);
            }
            if (r < M) {
                if (ATTN) {
#pragma unroll
                    for (int nt = 0; nt < 8; nt++) {
                        int c = cbase + nt * 8 + tg * 2;
                        __half2 p = __floats2half2_rn(v[nt][0], v[nt][1]);
                        hh[(size_t)r * halfN + (c >> 1)] = *(uint32_t*)&p;
                    }
                    if (tg == 0) {
                        int h0 = cbase >> 5;
                        asrc[(size_t)r * H + h0]     = ds0;
                        asrc[(size_t)r * H + h0 + 1] = ds1;
                        adst[(size_t)r * H + h0]     = dd0;
                        adst[(size_t)r * H + h0 + 1] = dd1;
                    }
                } else {
#pragma unroll
                    for (int nt = 0; nt < 8; nt++) {
                        int c = cbase + nt * 8 + tg * 2;
                        *(float2*)(C + (size_t)r * N + c) = make_float2(v[nt][0], v[nt][1]);
                    }
                }
            }
        }
    }
}

// ---------------- GAT aggregation over packed-half2 features, one warp per node ----------
// H=8: lane covers 8 dims (uint4 of half2s); H=4: lane covers 4 dims (uint2).
template <int H, bool SL, bool BN, bool FINAL>
__global__ void k_agg(const uint32_t* __restrict__ hh, const float* __restrict__ bias,
                      float* __restrict__ out, int n,
                      const float* __restrict__ bg, const float* __restrict__ bb,
                      const float* __restrict__ bmean, const float* __restrict__ bvar,
                      const float* __restrict__ resid,
                      const float* __restrict__ xi, const float* __restrict__ fcW,
                      const float* __restrict__ fcb, float* __restrict__ fout) {
    constexpr int D = H * 32;
    constexpr int ROW = D / 2;                 // uints per feature row
    constexpr int PL = (H == 8) ? 8 : 4;       // dims per lane
    int node = (blockIdx.x * blockDim.x + threadIdx.x) >> 5;
    int l = threadIdx.x & 31;
    if (node >= n) return;

    int myhead = (H == 8) ? (l >> 2) : (l >> 3);
    int d0 = PL * l;
    float ad = g_adst[node * H + myhead];
    int rs = g_rowptr[node], re = g_rowptr[node + 1];

    float den = 0.f;
    float acc[PL];
#pragma unroll
    for (int q = 0; q < PL; q++) acc[q] = 0.f;

    auto gather = [&](int s, float ex) {
        if (H == 8) {
            uint4 u = *(const uint4*)(hh + (size_t)s * ROW + (d0 >> 1));
            float2 f0 = __half22float2(*(__half2*)&u.x);
            float2 f1 = __half22float2(*(__half2*)&u.y);
            float2 f2 = __half22float2(*(__half2*)&u.z);
            float2 f3 = __half22float2(*(__half2*)&u.w);
            acc[0] = fmaf(ex, f0.x, acc[0]); acc[1] = fmaf(ex, f0.y, acc[1]);
            acc[2] = fmaf(ex, f1.x, acc[2]); acc[3] = fmaf(ex, f1.y, acc[3]);
            acc[4] = fmaf(ex, f2.x, acc[4]); acc[5] = fmaf(ex, f2.y, acc[5]);
            acc[6] = fmaf(ex, f3.x, acc[6]); acc[7] = fmaf(ex, f3.y, acc[7]);
        } else {
            uint2 u = *(const uint2*)(hh + (size_t)s * ROW + (d0 >> 1));
            float2 f0 = __half22float2(*(__half2*)&u.x);
            float2 f1 = __half22float2(*(__half2*)&u.y);
            acc[0] = fmaf(ex, f0.x, acc[0]); acc[1] = fmaf(ex, f0.y, acc[1]);
            acc[2] = fmaf(ex, f1.x, acc[2]); acc[3] = fmaf(ex, f1.y, acc[3]);
        }
    };

    if (SL) {
        float t = g_asrc[node * H + myhead] + ad;
        t = (t > 0.f) ? t : 0.2f * t;
        float ex = __expf(t);
        den += ex;
        gather(node, ex);
    }
    int j = rs;
    for (; j + 1 < re; j += 2) {
        int s0 = g_col[j];
        int s1 = g_col[j + 1];
        float t0 = g_asrc[s0 * H + myhead] + ad;
        float t1 = g_asrc[s1 * H + myhead] + ad;
        t0 = (t0 > 0.f) ? t0 : 0.2f * t0;
        t1 = (t1 > 0.f) ? t1 : 0.2f * t1;
        float e0 = __expf(t0);
        float e1 = __expf(t1);
        den += e0 + e1;
        gather(s0, e0);
        gather(s1, e1);
    }
    if (j < re) {
        int s = g_col[j];
        float t = g_asrc[s * H + myhead] + ad;
        t = (t > 0.f) ? t : 0.2f * t;
        float ex = __expf(t);
        den += ex;
        gather(node >= 0 ? s : s, ex);
    }

    float inv = 1.f / (den + 1e-16f);
    float o[PL];
#pragma unroll
    for (int q = 0; q < PL; q++) o[q] = acc[q] * inv + bias[d0 + q];

    if (BN) {
#pragma unroll
        for (int q = 0; q < PL; q += 4) {
            float4 gg = *(const float4*)(bg + d0 + q);
            float4 bbv = *(const float4*)(bb + d0 + q);
            float4 mm = *(const float4*)(bmean + d0 + q);
            float4 vv = *(const float4*)(bvar + d0 + q);
            float rr[4] = { 0.f, 0.f, 0.f, 0.f };
            if (resid) {
                float4 r4 = *(const float4*)(resid + (size_t)node * D + d0 + q);
                rr[0] = r4.x; rr[1] = r4.y; rr[2] = r4.z; rr[3] = r4.w;
            }
            float gx[4] = { gg.x, gg.y, gg.z, gg.w }, bx[4] = { bbv.x, bbv.y, bbv.z, bbv.w };
            float mx[4] = { mm.x, mm.y, mm.z, mm.w }, vx[4] = { vv.x, vv.y, vv.z, vv.w };
#pragma unroll
            for (int q2 = 0; q2 < 4; q2++) {
                float val = (o[q + q2] - mx[q2]) * rsqrtf(vx[q2] + 1e-5f) * gx[q2] + bx[q2] + rr[q2];
                o[q + q2] = (val > 0.f) ? val : expm1f(val);
            }
        }
    }

    if (!FINAL) {
#pragma unroll
        for (int q = 0; q < PL; q += 4)
            *(float4*)(out + (size_t)node * D + d0 + q) =
                make_float4(o[q], o[q + 1], o[q + 2], o[q + 3]);
    } else {
        // (o + x_init) @ fcW + fcb, log_softmax; D == 128, PL == 4
        float4 x4 = *(const float4*)(xi + (size_t)node * 128 + d0);
        float v[4] = { o[0] + x4.x, o[1] + x4.y, o[2] + x4.z, o[3] + x4.w };
        float z0 = 0.f, z1 = 0.f;
#pragma unroll
        for (int q = 0; q < 4; q++) {
            z0 = fmaf(v[q], fcW[(d0 + q) * 2], z0);
            z1 = fmaf(v[q], fcW[(d0 + q) * 2 + 1], z1);
        }
#pragma unroll
        for (int off = 16; off; off >>= 1) {
            z0 += __shfl_down_sync(0xffffffffu, z0, off);
            z1 += __shfl_down_sync(0xffffffffu, z1, off);
        }
        if (l == 0) {
            z0 += fcb[0]; z1 += fcb[1];
            float mx = fmaxf(z0, z1);
            float lse = mx + logf(expf(z0 - mx) + expf(z1 - mx));
            fout[node * 2] = z0 - lse;
            fout[node * 2 + 1] = z1 - lse;
        }
    }
}

// ---------------- launch ----------------
extern "C" void kernel_launch(void* const* d_in, const int* in_sizes, int n_in,
                              void* d_out, int out_size) {
    const float* x   = (const float*)d_in[0];
    const int*   ei  = (const int*)d_in[1];
    const float* W1  = (const float*)d_in[2];
    const float* a1s = (const float*)d_in[3];
    const float* a1d = (const float*)d_in[4];
    const float* b1  = (const float*)d_in[5];
    const float* g1  = (const float*)d_in[6];
    const float* be1 = (const float*)d_in[7];
    const float* m1  = (const float*)d_in[8];
    const float* v1  = (const float*)d_in[9];
    const float* W2  = (const float*)d_in[10];
    const float* a2s = (const float*)d_in[11];
    const float* a2d = (const float*)d_in[12];
    const float* b2  = (const float*)d_in[13];
    const float* g2  = (const float*)d_in[14];
    const float* be2 = (const float*)d_in[15];
    const float* m2  = (const float*)d_in[16];
    const float* v2  = (const float*)d_in[17];
    const float* W3  = (const float*)d_in[18];
    const float* a3s = (const float*)d_in[19];
    const float* a3d = (const float*)d_in[20];
    const float* b3  = (const float*)d_in[21];
    const float* fcW = (const float*)d_in[22];
    const float* fcb = (const float*)d_in[23];
    const float* skW = (const float*)d_in[24];
    const float* skb = (const float*)d_in[25];
    const float* temp = (const float*)d_in[26];

    int n = in_sizes[0] / FIN;   // 50000
    int e = in_sizes[1] / 2;     // 800000
    const int* src = ei;
    const int* dst = ei + e;

    float *buf2, *buf3, *xinit, *asrc, *adst;
    uint32_t* hh;
    cudaGetSymbolAddress((void**)&hh, g_hh);
    cudaGetSymbolAddress((void**)&buf2, g_buf2);
    cudaGetSymbolAddress((void**)&buf3, g_buf3);
    cudaGetSymbolAddress((void**)&xinit, g_xinit);
    cudaGetSymbolAddress((void**)&asrc, g_asrc);
    cudaGetSymbolAddress((void**)&adst, g_adst);

    int nb256 = (n + 255) / 256;
    int eb256 = (e + 255) / 256;
    int wg1 = (n * 32 + 255) / 256;    // one warp per node
    int gm = (n + 127) / 128;

    // CSR build (by destination)
    k_zero<<<nb256, 256>>>(n);
    k_count<<<eb256, 256>>>(dst, e);
    k_scan<<<1, 1024>>>(n);
    k_scatter<<<eb256, 256>>>(src, dst, e);

    // skip connection: x_init = x @ skW + skb (fp32 out)
    k_mgemm<false><<<dim3(1, gm), 256>>>(x, skW, xinit, nullptr, n, 128, FIN, skb, nullptr,
                                         nullptr, nullptr, nullptr, nullptr, 4);

    // ---- layer 1 (no self loops) ----
    k_mgemm<true><<<dim3(2, gm), 256>>>(x, W1, nullptr, hh, n, 256, FIN, nullptr, nullptr,
                                        asrc, adst, a1s, a1d, 8);
    k_agg<8, false, true, false><<<wg1, 256>>>(hh, b1, buf2, n, g1, be1, m1, v1, nullptr,
                                               nullptr, nullptr, nullptr, nullptr);

    // ---- layer 2 (self loops, residual) ----
    k_mgemm<true><<<dim3(2, gm), 256>>>(buf2, W2, nullptr, hh, n, 256, 256, nullptr, nullptr,
                                        asrc, adst, a2s, a2d, 8);
    k_agg<8, true, true, false><<<wg1, 256>>>(hh, b2, buf3, n, g2, be2, m2, v2, buf2,
                                              nullptr, nullptr, nullptr, nullptr);

    // ---- layer 3 (self loops, temp folded into GEMM scale), fused final ----
    k_mgemm<true><<<dim3(1, gm), 256>>>(buf3, W3, nullptr, hh, n, 128, 256, nullptr, temp,
                                        asrc, adst, a3s, a3d, 4);
    k_agg<4, true, false, true><<<wg1, 256>>>(hh, b3, nullptr, n, nullptr, nullptr, nullptr,
                                              nullptr, nullptr, xinit, fcW, fcb, (float*)d_out);
}

// round 9
// speedup vs baseline: 2.0284x; 1.1405x over previous
#include <cuda_runtime.h>
#include <cuda_fp16.h>
#include <cuda_bf16.h>
#include <math.h>
#include <cstdint>

#define NN 50000
#define EE 800000
#define FIN 165

// ---------------- scratch (device globals; no allocation allowed) ----------------
__device__ uint32_t g_hh[NN * 128];     // packed half2 features
__device__ float g_buf2[NN * 256];
__device__ float g_buf3[NN * 256];
__device__ float g_xinit[NN * 128];
__device__ float g_asrc[NN * 8];
__device__ float g_adst[NN * 8];
__device__ int   g_rowptr[NN + 1];
__device__ int   g_cursor[NN];
__device__ int   g_col[EE];

// ---------------- CSR build (by destination) ----------------
__global__ void k_zero(int n) {
    int i = blockIdx.x * blockDim.x + threadIdx.x;
    if (i < n) g_cursor[i] = 0;
}
__global__ void k_count(const int* __restrict__ dst, int e) {
    int i = blockIdx.x * blockDim.x + threadIdx.x;
    if (i < e) atomicAdd(&g_cursor[dst[i]], 1);
}
__global__ void k_scan(int n) {
    __shared__ int sh[1024];
    int t = threadIdx.x;
    int C = (n + 1023) / 1024;
    int base = t * C;
    int local = 0;
    for (int j = 0; j < C; j++) { int i = base + j; if (i < n) local += g_cursor[i]; }
    sh[t] = local;
    __syncthreads();
    for (int off = 1; off < 1024; off <<= 1) {
        int v = (t >= off) ? sh[t - off] : 0;
        __syncthreads();
        sh[t] += v;
        __syncthreads();
    }
    int run = sh[t] - local;
    for (int j = 0; j < C; j++) {
        int i = base + j;
        if (i < n) { int d = g_cursor[i]; g_rowptr[i] = run; g_cursor[i] = run; run += d; }
    }
    if (t == 1023) g_rowptr[n] = sh[1023];
}
__global__ void k_scatter(const int* __restrict__ src, const int* __restrict__ dst, int e) {
    int i = blockIdx.x * blockDim.x + threadIdx.x;
    if (i >= e) return;
    int pos = atomicAdd(&g_cursor[dst[i]], 1);
    g_col[pos] = src[i];
}

// ---------------- bf16 split + mma helper ----------------
__device__ __forceinline__ void split_bf16(float v, __nv_bfloat16& h, __nv_bfloat16& l) {
    h = __float2bfloat16_rn(v);
    l = __float2bfloat16_rn(v - __bfloat162float(h));
}

__device__ __forceinline__ void mma16816(float* c, const uint32_t* a, const uint32_t* b) {
    asm volatile(
        "mma.sync.aligned.m16n8k16.row.col.f32.bf16.bf16.f32 "
        "{%0,%1,%2,%3}, {%4,%5,%6,%7}, {%8,%9}, {%0,%1,%2,%3};"
        : "+f"(c[0]), "+f"(c[1]), "+f"(c[2]), "+f"(c[3])
        : "r"(a[0]), "r"(a[1]), "r"(a[2]), "r"(a[3]), "r"(b[0]), "r"(b[1]));
}

#define LDS_STRIDE 18

// ================= bf16x3 tensor-core GEMM, 128x128 block, BK=16, double-buffered =========
// FUSE_SKIP=true : layer-1 + skip fused. blockIdx.x==0 computes x@skW+skb -> fp32 Cskip;
//                  blocks 1..NT compute x@W1 -> half2 hh + fused attention dots.
// FUSE_SKIP=false: plain ATTN GEMM (A@B -> half2 hh + attention dots), grid.x = N/128.
template <bool FUSE_SKIP>
__global__ void __launch_bounds__(256, 2)
k_mgemm(const float* __restrict__ A, const float* __restrict__ B, int Kdim,
        const float* __restrict__ Bskip, float* __restrict__ Cskip,
        const float* __restrict__ skb,
        uint32_t* __restrict__ hh, int M, int N,        // N = ATTN output width
        const float* __restrict__ scale,
        float* __restrict__ asrc, float* __restrict__ adst,
        const float* __restrict__ a_s, const float* __restrict__ a_d, int H) {
    __shared__ __align__(16) __nv_bfloat16 AsH[2][128][LDS_STRIDE];
    __shared__ __align__(16) __nv_bfloat16 AsL[2][128][LDS_STRIDE];
    __shared__ __align__(16) __nv_bfloat16 BsH[2][128][LDS_STRIDE];
    __shared__ __align__(16) __nv_bfloat16 BsL[2][128][LDS_STRIDE];

    int tid = threadIdx.x;
    int wid = tid >> 5;
    int lane = tid & 31;
    int g = lane >> 2, tg = lane & 3;
    int warp_m = wid & 3;
    int warp_n = wid >> 2;
    int bm = blockIdx.y * 128;

    const bool isSkip = FUSE_SKIP && (blockIdx.x == 0);
    // column base within the ATTN output (for non-skip blocks)
    int bn = FUSE_SKIP ? ((int)blockIdx.x - 1) * 128 : (int)blockIdx.x * 128;
    const float* Bp = isSkip ? Bskip : B;
    int Bstride = isSkip ? 128 : N;
    int bcol = isSkip ? 0 : bn;

    float acc[2][8][4];
#pragma unroll
    for (int mt = 0; mt < 2; mt++)
#pragma unroll
        for (int nt = 0; nt < 8; nt++)
#pragma unroll
            for (int q = 0; q < 4; q++) acc[mt][nt][q] = 0.f;

    float av[8], bv[8];
    int K = Kdim;
    int nk = (K + 15) >> 4;

    {
#pragma unroll
        for (int i = 0; i < 8; i++) {
            int idx = tid + i * 256;
            int r = idx >> 4, kk = idx & 15;
            int gr = bm + r;
            av[i] = (gr < M && kk < K) ? A[(size_t)gr * K + kk] : 0.f;
        }
#pragma unroll
        for (int i = 0; i < 8; i++) {
            int idx = tid + i * 256;
            int k = idx >> 7, nn = idx & 127;
            bv[i] = (k < K) ? Bp[(size_t)k * Bstride + bcol + nn] : 0.f;
        }
#pragma unroll
        for (int i = 0; i < 8; i++) {
            int idx = tid + i * 256;
            int r = idx >> 4, kk = idx & 15;
            __nv_bfloat16 h, l; split_bf16(av[i], h, l);
            AsH[0][r][kk] = h; AsL[0][r][kk] = l;
        }
#pragma unroll
        for (int i = 0; i < 8; i++) {
            int idx = tid + i * 256;
            int k = idx >> 7, nn = idx & 127;
            __nv_bfloat16 h, l; split_bf16(bv[i], h, l);
            BsH[0][nn][k] = h; BsL[0][nn][k] = l;
        }
    }
    __syncthreads();

    for (int t = 0; t < nk; t++) {
        int cur = t & 1;
        if (t + 1 < nk) {
            int k0 = (t + 1) << 4;
#pragma unroll
            for (int i = 0; i < 8; i++) {
                int idx = tid + i * 256;
                int r = idx >> 4, kk = idx & 15;
                int gr = bm + r, gk = k0 + kk;
                av[i] = (gr < M && gk < K) ? A[(size_t)gr * K + gk] : 0.f;
            }
#pragma unroll
            for (int i = 0; i < 8; i++) {
                int idx = tid + i * 256;
                int k = idx >> 7, nn = idx & 127;
                int gk = k0 + k;
                bv[i] = (gk < K) ? Bp[(size_t)gk * Bstride + bcol + nn] : 0.f;
            }
        }
        {
            uint32_t aH[2][4], aL[2][4];
#pragma unroll
            for (int mt = 0; mt < 2; mt++) {
                int r0 = warp_m * 32 + mt * 16;
                aH[mt][0] = *(const uint32_t*)&AsH[cur][r0 + g][tg * 2];
                aH[mt][1] = *(const uint32_t*)&AsH[cur][r0 + g + 8][tg * 2];
                aH[mt][2] = *(const uint32_t*)&AsH[cur][r0 + g][tg * 2 + 8];
                aH[mt][3] = *(const uint32_t*)&AsH[cur][r0 + g + 8][tg * 2 + 8];
                aL[mt][0] = *(const uint32_t*)&AsL[cur][r0 + g][tg * 2];
                aL[mt][1] = *(const uint32_t*)&AsL[cur][r0 + g + 8][tg * 2];
                aL[mt][2] = *(const uint32_t*)&AsL[cur][r0 + g][tg * 2 + 8];
                aL[mt][3] = *(const uint32_t*)&AsL[cur][r0 + g + 8][tg * 2 + 8];
            }
#pragma unroll
            for (int nt = 0; nt < 8; nt++) {
                int n0 = warp_n * 64 + nt * 8 + g;
                uint32_t bH[2], bL[2];
                bH[0] = *(const uint32_t*)&BsH[cur][n0][tg * 2];
                bH[1] = *(const uint32_t*)&BsH[cur][n0][tg * 2 + 8];
                bL[0] = *(const uint32_t*)&BsL[cur][n0][tg * 2];
                bL[1] = *(const uint32_t*)&BsL[cur][n0][tg * 2 + 8];
#pragma unroll
                for (int mt = 0; mt < 2; mt++) {
                    mma16816(acc[mt][nt], aH[mt], bH);
                    mma16816(acc[mt][nt], aH[mt], bL);
                    mma16816(acc[mt][nt], aL[mt], bH);
                }
            }
        }
        if (t + 1 < nk) {
            __syncthreads();
            int nxt = cur ^ 1;
#pragma unroll
            for (int i = 0; i < 8; i++) {
                int idx = tid + i * 256;
                int r = idx >> 4, kk = idx & 15;
                __nv_bfloat16 h, l; split_bf16(av[i], h, l);
                AsH[nxt][r][kk] = h; AsL[nxt][r][kk] = l;
            }
#pragma unroll
            for (int i = 0; i < 8; i++) {
                int idx = tid + i * 256;
                int k = idx >> 7, nn = idx & 127;
                __nv_bfloat16 h, l; split_bf16(bv[i], h, l);
                BsH[nxt][nn][k] = h; BsL[nxt][nn][k] = l;
            }
            __syncthreads();
        }
    }

    // ---- epilogue ----
    float scl = scale ? *scale : 1.0f;
    int cb_local = warp_n * 64;            // within this block's 128 cols
    int cbase = bn + cb_local;             // within ATTN output (valid when !isSkip)
    int halfN = N >> 1;
#pragma unroll
    for (int mt = 0; mt < 2; mt++) {
#pragma unroll
        for (int rh = 0; rh < 2; rh++) {
            int r = bm + warp_m * 32 + mt * 16 + rh * 8 + g;
            float v[8][2];
            float ds0 = 0.f, dd0 = 0.f, ds1 = 0.f, dd1 = 0.f;
#pragma unroll
            for (int nt = 0; nt < 8; nt++) {
                float v0 = acc[mt][nt][rh * 2 + 0] * scl;
                float v1 = acc[mt][nt][rh * 2 + 1] * scl;
                if (isSkip) {
                    int c = cb_local + nt * 8 + tg * 2;
                    v0 += skb[c]; v1 += skb[c + 1];
                } else {
                    int c = cbase + nt * 8 + tg * 2;
                    float s0 = a_s[c], s1 = a_s[c + 1];
                    float d0 = a_d[c], d1 = a_d[c + 1];
                    if (nt < 4) {
                        ds0 = fmaf(v0, s0, fmaf(v1, s1, ds0));
                        dd0 = fmaf(v0, d0, fmaf(v1, d1, dd0));
                    } else {
                        ds1 = fmaf(v0, s0, fmaf(v1, s1, ds1));
                        dd1 = fmaf(v0, d0, fmaf(v1, d1, dd1));
                    }
                }
                v[nt][0] = v0; v[nt][1] = v1;
            }
            if (!isSkip) {
                ds0 += __shfl_xor_sync(0xffffffffu, ds0, 1);
                ds0 += __shfl_xor_sync(0xffffffffu, ds0, 2);
                dd0 += __shfl_xor_sync(0xffffffffu, dd0, 1);
                dd0 += __shfl_xor_sync(0xffffffffu, dd0, 2);
                ds1 += __shfl_xor_sync(0xffffffffu, ds1, 1);
                ds1 += __shfl_xor_sync(0xffffffffu, ds1, 2);
                dd1 += __shfl_xor_sync(0xffffffffu, dd1, 1);
                dd1 += __shfl_xor_sync(0xffffffffu, dd1, 2);
            }
            if (r < M) {
                if (isSkip) {
#pragma unroll
                    for (int nt = 0; nt < 8; nt++) {
                        int c = cb_local + nt * 8 + tg * 2;
                        *(float2*)(Cskip + (size_t)r * 128 + c) = make_float2(v[nt][0], v[nt][1]);
                    }
                } else {
#pragma unroll
                    for (int nt = 0; nt < 8; nt++) {
                        int c = cbase + nt * 8 + tg * 2;
                        __half2 p = __floats2half2_rn(v[nt][0], v[nt][1]);
                        hh[(size_t)r * halfN + (c >> 1)] = *(uint32_t*)&p;
                    }
                    if (tg == 0) {
                        int h0 = cbase >> 5;
                        asrc[(size_t)r * H + h0]     = ds0;
                        asrc[(size_t)r * H + h0 + 1] = ds1;
                        adst[(size_t)r * H + h0]     = dd0;
                        adst[(size_t)r * H + h0 + 1] = dd1;
                    }
                }
            }
        }
    }
}

// ---------------- GAT aggregation over packed-half2 features, one warp per node ----------
template <int H, bool SL, bool BN, bool FINAL>
__global__ void k_agg(const uint32_t* __restrict__ hh, const float* __restrict__ bias,
                      float* __restrict__ out, int n,
                      const float* __restrict__ bg, const float* __restrict__ bb,
                      const float* __restrict__ bmean, const float* __restrict__ bvar,
                      const float* __restrict__ resid,
                      const float* __restrict__ xi, const float* __restrict__ fcW,
                      const float* __restrict__ fcb, float* __restrict__ fout) {
    constexpr int D = H * 32;
    constexpr int ROW = D / 2;
    constexpr int PL = (H == 8) ? 8 : 4;
    int node = (blockIdx.x * blockDim.x + threadIdx.x) >> 5;
    int l = threadIdx.x & 31;
    if (node >= n) return;

    int myhead = (H == 8) ? (l >> 2) : (l >> 3);
    int d0 = PL * l;
    float ad = g_adst[node * H + myhead];
    int rs = g_rowptr[node], re = g_rowptr[node + 1];

    float den = 0.f;
    float acc[PL];
#pragma unroll
    for (int q = 0; q < PL; q++) acc[q] = 0.f;

    auto gather = [&](int s, float ex) {
        if (H == 8) {
            uint4 u = *(const uint4*)(hh + (size_t)s * ROW + (d0 >> 1));
            float2 f0 = __half22float2(*(__half2*)&u.x);
            float2 f1 = __half22float2(*(__half2*)&u.y);
            float2 f2 = __half22float2(*(__half2*)&u.z);
            float2 f3 = __half22float2(*(__half2*)&u.w);
            acc[0] = fmaf(ex, f0.x, acc[0]); acc[1] = fmaf(ex, f0.y, acc[1]);
            acc[2] = fmaf(ex, f1.x, acc[2]); acc[3] = fmaf(ex, f1.y, acc[3]);
            acc[4] = fmaf(ex, f2.x, acc[4]); acc[5] = fmaf(ex, f2.y, acc[5]);
            acc[6] = fmaf(ex, f3.x, acc[6]); acc[7] = fmaf(ex, f3.y, acc[7]);
        } else {
            uint2 u = *(const uint2*)(hh + (size_t)s * ROW + (d0 >> 1));
            float2 f0 = __half22float2(*(__half2*)&u.x);
            float2 f1 = __half22float2(*(__half2*)&u.y);
            acc[0] = fmaf(ex, f0.x, acc[0]); acc[1] = fmaf(ex, f0.y, acc[1]);
            acc[2] = fmaf(ex, f1.x, acc[2]); acc[3] = fmaf(ex, f1.y, acc[3]);
        }
    };
    auto logit = [&](int s) {
        float t = g_asrc[s * H + myhead] + ad;
        t = (t > 0.f) ? t : 0.2f * t;
        return __expf(t);
    };

    if (SL) {
        float ex = logit(node);
        den += ex;
        gather(node, ex);
    }
    int j = rs;
    for (; j + 3 < re; j += 4) {
        int s0 = g_col[j], s1 = g_col[j + 1], s2 = g_col[j + 2], s3 = g_col[j + 3];
        float e0 = logit(s0);
        float e1 = logit(s1);
        float e2 = logit(s2);
        float e3 = logit(s3);
        den += (e0 + e1) + (e2 + e3);
        gather(s0, e0);
        gather(s1, e1);
        gather(s2, e2);
        gather(s3, e3);
    }
    for (; j < re; j++) {
        int s = g_col[j];
        float ex = logit(s);
        den += ex;
        gather(s, ex);
    }

    float inv = 1.f / (den + 1e-16f);
    float o[PL];
#pragma unroll
    for (int q = 0; q < PL; q++) o[q] = acc[q] * inv + bias[d0 + q];

    if (BN) {
#pragma unroll
        for (int q = 0; q < PL; q += 4) {
            float4 gg = *(const float4*)(bg + d0 + q);
            float4 bbv = *(const float4*)(bb + d0 + q);
            float4 mm = *(const float4*)(bmean + d0 + q);
            float4 vv = *(const float4*)(bvar + d0 + q);
            float rr[4] = { 0.f, 0.f, 0.f, 0.f };
            if (resid) {
                float4 r4 = *(const float4*)(resid + (size_t)node * D + d0 + q);
                rr[0] = r4.x; rr[1] = r4.y; rr[2] = r4.z; rr[3] = r4.w;
            }
            float gx[4] = { gg.x, gg.y, gg.z, gg.w }, bx[4] = { bbv.x, bbv.y, bbv.z, bbv.w };
            float mx[4] = { mm.x, mm.y, mm.z, mm.w }, vx[4] = { vv.x, vv.y, vv.z, vv.w };
#pragma unroll
            for (int q2 = 0; q2 < 4; q2++) {
                float val = (o[q + q2] - mx[q2]) * rsqrtf(vx[q2] + 1e-5f) * gx[q2] + bx[q2] + rr[q2];
                o[q + q2] = (val > 0.f) ? val : expm1f(val);
            }
        }
    }

    if (!FINAL) {
#pragma unroll
        for (int q = 0; q < PL; q += 4)
            *(float4*)(out + (size_t)node * D + d0 + q) =
                make_float4(o[q], o[q + 1], o[q + 2], o[q + 3]);
    } else {
        float4 x4 = *(const float4*)(xi + (size_t)node * 128 + d0);
        float v[4] = { o[0] + x4.x, o[1] + x4.y, o[2] + x4.z, o[3] + x4.w };
        float z0 = 0.f, z1 = 0.f;
#pragma unroll
        for (int q = 0; q < 4; q++) {
            z0 = fmaf(v[q], fcW[(d0 + q) * 2], z0);
            z1 = fmaf(v[q], fcW[(d0 + q) * 2 + 1], z1);
        }
#pragma unroll
        for (int off = 16; off; off >>= 1) {
            z0 += __shfl_down_sync(0xffffffffu, z0, off);
            z1 += __shfl_down_sync(0xffffffffu, z1, off);
        }
        if (l == 0) {
            z0 += fcb[0]; z1 += fcb[1];
            float mx = fmaxf(z0, z1);
            float lse = mx + logf(expf(z0 - mx) + expf(z1 - mx));
            fout[node * 2] = z0 - lse;
            fout[node * 2 + 1] = z1 - lse;
        }
    }
}

// ---------------- launch ----------------
extern "C" void kernel_launch(void* const* d_in, const int* in_sizes, int n_in,
                              void* d_out, int out_size) {
    const float* x   = (const float*)d_in[0];
    const int*   ei  = (const int*)d_in[1];
    const float* W1  = (const float*)d_in[2];
    const float* a1s = (const float*)d_in[3];
    const float* a1d = (const float*)d_in[4];
    const float* b1  = (const float*)d_in[5];
    const float* g1  = (const float*)d_in[6];
    const float* be1 = (const float*)d_in[7];
    const float* m1  = (const float*)d_in[8];
    const float* v1  = (const float*)d_in[9];
    const float* W2  = (const float*)d_in[10];
    const float* a2s = (const float*)d_in[11];
    const float* a2d = (const float*)d_in[12];
    const float* b2  = (const float*)d_in[13];
    const float* g2  = (const float*)d_in[14];
    const float* be2 = (const float*)d_in[15];
    const float* m2  = (const float*)d_in[16];
    const float* v2  = (const float*)d_in[17];
    const float* W3  = (const float*)d_in[18];
    const float* a3s = (const float*)d_in[19];
    const float* a3d = (const float*)d_in[20];
    const float* b3  = (const float*)d_in[21];
    const float* fcW = (const float*)d_in[22];
    const float* fcb = (const float*)d_in[23];
    const float* skW = (const float*)d_in[24];
    const float* skb = (const float*)d_in[25];
    const float* temp = (const float*)d_in[26];

    int n = in_sizes[0] / FIN;   // 50000
    int e = in_sizes[1] / 2;     // 800000
    const int* src = ei;
    const int* dst = ei + e;

    float *buf2, *buf3, *xinit, *asrc, *adst;
    uint32_t* hh;
    cudaGetSymbolAddress((void**)&hh, g_hh);
    cudaGetSymbolAddress((void**)&buf2, g_buf2);
    cudaGetSymbolAddress((void**)&buf3, g_buf3);
    cudaGetSymbolAddress((void**)&xinit, g_xinit);
    cudaGetSymbolAddress((void**)&asrc, g_asrc);
    cudaGetSymbolAddress((void**)&adst, g_adst);

    int nb256 = (n + 255) / 256;
    int eb256 = (e + 255) / 256;
    int wg1 = (n * 32 + 255) / 256;
    int gm = (n + 127) / 128;

    // CSR build (by destination)
    k_zero<<<nb256, 256>>>(n);
    k_count<<<eb256, 256>>>(dst, e);
    k_scan<<<1, 1024>>>(n);
    k_scatter<<<eb256, 256>>>(src, dst, e);

    // ---- layer 1 + skip, fused (grid.x: 0 = skip, 1..2 = W1) ----
    k_mgemm<true><<<dim3(3, gm), 256>>>(x, W1, FIN, skW, xinit, skb,
                                        hh, n, 256, nullptr,
                                        asrc, adst, a1s, a1d, 8);
    k_agg<8, false, true, false><<<wg1, 256>>>(hh, b1, buf2, n, g1, be1, m1, v1, nullptr,
                                               nullptr, nullptr, nullptr, nullptr);

    // ---- layer 2 (self loops, residual) ----
    k_mgemm<false><<<dim3(2, gm), 256>>>(buf2, W2, 256, nullptr, nullptr, nullptr,
                                         hh, n, 256, nullptr,
                                         asrc, adst, a2s, a2d, 8);
    k_agg<8, true, true, false><<<wg1, 256>>>(hh, b2, buf3, n, g2, be2, m2, v2, buf2,
                                              nullptr, nullptr, nullptr, nullptr);

    // ---- layer 3 (self loops, temp folded into GEMM scale), fused final ----
    k_mgemm<false><<<dim3(1, gm), 256>>>(buf3, W3, 256, nullptr, nullptr, nullptr,
                                         hh, n, 128, temp,
                                         asrc, adst, a3s, a3d, 4);
    k_agg<4, true, false, true><<<wg1, 256>>>(hh, b3, nullptr, n, nullptr, nullptr, nullptr,
                                              nullptr, nullptr, xinit, fcW, fcb, (float*)d_out);
}